// round 2
// baseline (speedup 1.0000x reference)
#include <cuda_runtime.h>

// Problem constants
#define EMB   1024
#define NH    16
#define HD    64
#define BATCH 2
#define SEQ   2048
#define MTOT  (BATCH*SEQ)   // 4096

// Scratch (device globals — no allocation allowed)
__device__ float g_q[(size_t)BATCH*NH*SEQ*HD];   // [B,H,S,D]
__device__ float g_k[(size_t)BATCH*NH*SEQ*HD];
__device__ float g_v[(size_t)BATCH*NH*SEQ*HD];
__device__ float g_ctx[(size_t)MTOT*EMB];        // [B,S,E]

// ---------------------------------------------------------------------------
// GEMM: C[4096,1024] = A[4096,1024] @ W[1024,1024]
// 128x128 tile, BK=16, 256 threads, 8x8 per thread (2x2 raked 4x4 frags).
// MODE 0: scatter epilogue to [B,H,S,D]; MODE 1: plain row-major.
// ---------------------------------------------------------------------------
template<int MODE>
__global__ __launch_bounds__(256) void gemm_kernel(const float* __restrict__ A,
                                                   const float* __restrict__ W,
                                                   float* __restrict__ Cout)
{
    constexpr int LDS = 132;               // padded stride (floats)
    __shared__ float As[16 * LDS];         // As[k][m] (transposed)
    __shared__ float Bs[16 * LDS];         // Bs[k][n]

    const int t  = threadIdx.x;
    const int tx = t & 15;                 // 0..15 -> n
    const int ty = t >> 4;                 // 0..15 -> m
    const int m0 = blockIdx.y * 128;
    const int n0 = blockIdx.x * 128;

    float acc[2][2][4][4];
#pragma unroll
    for (int a = 0; a < 2; a++)
#pragma unroll
        for (int b = 0; b < 2; b++)
#pragma unroll
            for (int i = 0; i < 4; i++)
#pragma unroll
                for (int j = 0; j < 4; j++) acc[a][b][i][j] = 0.f;

    for (int kt = 0; kt < EMB; kt += 16) {
        // Load A tile (128 rows x 16 k), transpose into As[k][m]
#pragma unroll
        for (int it = 0; it < 2; it++) {
            int f   = t + it * 256;        // 0..511 float4s
            int row = f >> 2;
            int c4  = (f & 3) << 2;
            float4 v = *reinterpret_cast<const float4*>(
                A + (size_t)(m0 + row) * EMB + kt + c4);
            As[(c4 + 0) * LDS + row] = v.x;
            As[(c4 + 1) * LDS + row] = v.y;
            As[(c4 + 2) * LDS + row] = v.z;
            As[(c4 + 3) * LDS + row] = v.w;
        }
        // Load B tile (16 k x 128 n)
#pragma unroll
        for (int it = 0; it < 2; it++) {
            int f   = t + it * 256;
            int row = f >> 5;
            int c4  = (f & 31) << 2;
            *reinterpret_cast<float4*>(&Bs[row * LDS + c4]) =
                *reinterpret_cast<const float4*>(
                    W + (size_t)(kt + row) * EMB + n0 + c4);
        }
        __syncthreads();

#pragma unroll
        for (int k = 0; k < 16; k++) {
            float4 a0 = *reinterpret_cast<float4*>(&As[k * LDS + ty * 4]);
            float4 a1 = *reinterpret_cast<float4*>(&As[k * LDS + 64 + ty * 4]);
            float4 b0 = *reinterpret_cast<float4*>(&Bs[k * LDS + tx * 4]);
            float4 b1 = *reinterpret_cast<float4*>(&Bs[k * LDS + 64 + tx * 4]);
            float av[2][4] = {{a0.x, a0.y, a0.z, a0.w}, {a1.x, a1.y, a1.z, a1.w}};
            float bv[2][4] = {{b0.x, b0.y, b0.z, b0.w}, {b1.x, b1.y, b1.z, b1.w}};
#pragma unroll
            for (int im = 0; im < 2; im++)
#pragma unroll
                for (int in = 0; in < 2; in++)
#pragma unroll
                    for (int i = 0; i < 4; i++)
#pragma unroll
                        for (int j = 0; j < 4; j++)
                            acc[im][in][i][j] = fmaf(av[im][i], bv[in][j],
                                                     acc[im][in][i][j]);
        }
        __syncthreads();
    }

    // Epilogue
#pragma unroll
    for (int im = 0; im < 2; im++) {
#pragma unroll
        for (int i = 0; i < 4; i++) {
            int m = m0 + im * 64 + ty * 4 + i;
#pragma unroll
            for (int in = 0; in < 2; in++) {
                int n = n0 + in * 64 + tx * 4;
                float4 v = make_float4(acc[im][in][i][0], acc[im][in][i][1],
                                       acc[im][in][i][2], acc[im][in][i][3]);
                if (MODE == 0) {
                    // scatter: [m=(b,s), n=(h,d)] -> [B,H,S,D]
                    int b = m >> 11, s = m & 2047;
                    int h = n >> 6,  d = n & 63;
                    *reinterpret_cast<float4*>(
                        Cout + (((size_t)(b * NH + h) * SEQ + s) * HD + d)) = v;
                } else {
                    *reinterpret_cast<float4*>(Cout + (size_t)m * EMB + n) = v;
                }
            }
        }
    }
}

// ---------------------------------------------------------------------------
// Flash attention, causal. One CTA per (64-row block, b*h). 128 threads.
// BM=BN=64, D=64. Online softmax in registers, P staged via smem.
// ---------------------------------------------------------------------------
__global__ __launch_bounds__(128) void attn_kernel()
{
    extern __shared__ float sm[];
    float* Qs = sm;                 // 64 x 65
    float* Ks = sm + 64 * 65;       // 64 x 65  (Ks[j][k])
    float* Vs = sm + 2 * 64 * 65;   // 64 x 65  (Vs[k][d])
    float* Ps = sm + 3 * 64 * 65;   // 64 x 65

    const int t  = threadIdx.x;
    const int tx = t & 7;           // column group (8 cols)
    const int ty = t >> 3;          // row group (4 rows)
    const int bh = blockIdx.y;      // 0..31
    const int rb = (gridDim.x - 1) - blockIdx.x;   // heavy blocks first
    const int m0 = rb * 64;

    // Load Q tile (64x64)
    const float* Qg = g_q + ((size_t)bh * SEQ + m0) * HD;
#pragma unroll
    for (int f = t; f < 1024; f += 128) {
        int row = f >> 4;
        int c4  = (f & 15) << 2;
        float4 v = reinterpret_cast<const float4*>(Qg)[f];
        Qs[row * 65 + c4 + 0] = v.x;
        Qs[row * 65 + c4 + 1] = v.y;
        Qs[row * 65 + c4 + 2] = v.z;
        Qs[row * 65 + c4 + 3] = v.w;
    }

    float mi[4], li[4], o[4][8];
#pragma unroll
    for (int i = 0; i < 4; i++) {
        mi[i] = -1e30f;
        li[i] = 0.f;
#pragma unroll
        for (int j = 0; j < 8; j++) o[i][j] = 0.f;
    }

    for (int jb = 0; jb <= rb; jb++) {
        __syncthreads();   // prior-iter readers done; also fences Q load (iter 0)

        const float* Kg = g_k + ((size_t)bh * SEQ + jb * 64) * HD;
        const float* Vg = g_v + ((size_t)bh * SEQ + jb * 64) * HD;
#pragma unroll
        for (int f = t; f < 1024; f += 128) {
            int row = f >> 4;
            int c4  = (f & 15) << 2;
            float4 v = reinterpret_cast<const float4*>(Kg)[f];
            Ks[row * 65 + c4 + 0] = v.x;
            Ks[row * 65 + c4 + 1] = v.y;
            Ks[row * 65 + c4 + 2] = v.z;
            Ks[row * 65 + c4 + 3] = v.w;
            float4 w = reinterpret_cast<const float4*>(Vg)[f];
            Vs[row * 65 + c4 + 0] = w.x;
            Vs[row * 65 + c4 + 1] = w.y;
            Vs[row * 65 + c4 + 2] = w.z;
            Vs[row * 65 + c4 + 3] = w.w;
        }
        __syncthreads();

        // S = Q @ K^T  (4x8 tile per thread, full K-dim)
        float c[4][8];
#pragma unroll
        for (int i = 0; i < 4; i++)
#pragma unroll
            for (int j = 0; j < 8; j++) c[i][j] = 0.f;

#pragma unroll 4
        for (int k = 0; k < 64; k++) {
            float q[4], kv[8];
#pragma unroll
            for (int i = 0; i < 4; i++) q[i] = Qs[(ty * 4 + i) * 65 + k];
#pragma unroll
            for (int j = 0; j < 8; j++) kv[j] = Ks[(tx * 8 + j) * 65 + k];
#pragma unroll
            for (int i = 0; i < 4; i++)
#pragma unroll
                for (int j = 0; j < 8; j++)
                    c[i][j] = fmaf(q[i], kv[j], c[i][j]);
        }

        // scale + causal mask + online softmax update
        const bool diag = (jb == rb);
#pragma unroll
        for (int i = 0; i < 4; i++) {
            int ig = m0 + ty * 4 + i;
            float rmax = -1e30f;
#pragma unroll
            for (int j = 0; j < 8; j++) {
                float s = c[i][j] * 0.125f;   // 1/sqrt(64)
                if (diag && (jb * 64 + tx * 8 + j) > ig) s = -1e30f;
                c[i][j] = s;
                rmax = fmaxf(rmax, s);
            }
            rmax = fmaxf(rmax, __shfl_xor_sync(0xffffffffu, rmax, 1));
            rmax = fmaxf(rmax, __shfl_xor_sync(0xffffffffu, rmax, 2));
            rmax = fmaxf(rmax, __shfl_xor_sync(0xffffffffu, rmax, 4));
            float mnew  = fmaxf(mi[i], rmax);
            float alpha = __expf(mi[i] - mnew);
            float rsum  = 0.f;
#pragma unroll
            for (int j = 0; j < 8; j++) {
                float p = __expf(c[i][j] - mnew);
                c[i][j] = p;
                rsum += p;
            }
            rsum += __shfl_xor_sync(0xffffffffu, rsum, 1);
            rsum += __shfl_xor_sync(0xffffffffu, rsum, 2);
            rsum += __shfl_xor_sync(0xffffffffu, rsum, 4);
            li[i] = li[i] * alpha + rsum;
            mi[i] = mnew;
#pragma unroll
            for (int j = 0; j < 8; j++) o[i][j] *= alpha;
        }

        // stage P, then O += P @ V
#pragma unroll
        for (int i = 0; i < 4; i++)
#pragma unroll
            for (int j = 0; j < 8; j++)
                Ps[(ty * 4 + i) * 65 + tx * 8 + j] = c[i][j];
        __syncthreads();

#pragma unroll 4
        for (int k = 0; k < 64; k++) {
            float p[4], v8[8];
#pragma unroll
            for (int i = 0; i < 4; i++) p[i] = Ps[(ty * 4 + i) * 65 + k];
#pragma unroll
            for (int j = 0; j < 8; j++) v8[j] = Vs[k * 65 + tx * 8 + j];
#pragma unroll
            for (int i = 0; i < 4; i++)
#pragma unroll
                for (int j = 0; j < 8; j++)
                    o[i][j] = fmaf(p[i], v8[j], o[i][j]);
        }
    }

    // Epilogue: normalize and write to g_ctx [B,S,E]
    const int b = bh >> 4, h = bh & 15;
#pragma unroll
    for (int i = 0; i < 4; i++) {
        float inv = 1.0f / li[i];
        int s = m0 + ty * 4 + i;
        float* dst = g_ctx + ((size_t)(b * SEQ + s)) * EMB + h * HD + tx * 8;
        float4 v0 = make_float4(o[i][0] * inv, o[i][1] * inv,
                                o[i][2] * inv, o[i][3] * inv);
        float4 v1 = make_float4(o[i][4] * inv, o[i][5] * inv,
                                o[i][6] * inv, o[i][7] * inv);
        *reinterpret_cast<float4*>(dst)     = v0;
        *reinterpret_cast<float4*>(dst + 4) = v1;
    }
}

// ---------------------------------------------------------------------------
extern "C" void kernel_launch(void* const* d_in, const int* in_sizes, int n_in,
                              void* d_out, int out_size)
{
    const float* x  = (const float*)d_in[0];
    const float* wq = (const float*)d_in[1];
    const float* wk = (const float*)d_in[2];
    const float* wv = (const float*)d_in[3];
    const float* wo = (const float*)d_in[4];
    float* out = (float*)d_out;

    void *pq, *pk, *pv, *pctx;
    cudaGetSymbolAddress(&pq,   g_q);
    cudaGetSymbolAddress(&pk,   g_k);
    cudaGetSymbolAddress(&pv,   g_v);
    cudaGetSymbolAddress(&pctx, g_ctx);

    const int attn_smem = 4 * 64 * 65 * (int)sizeof(float);   // 66560 B
    cudaFuncSetAttribute(attn_kernel,
                         cudaFuncAttributeMaxDynamicSharedMemorySize, attn_smem);

    dim3 gg(EMB / 128, MTOT / 128);   // (8, 32)
    gemm_kernel<0><<<gg, 256>>>(x, wq, (float*)pq);
    gemm_kernel<0><<<gg, 256>>>(x, wk, (float*)pk);
    gemm_kernel<0><<<gg, 256>>>(x, wv, (float*)pv);

    attn_kernel<<<dim3(SEQ / 64, BATCH * NH), 128, attn_smem>>>();

    gemm_kernel<1><<<gg, 256>>>((const float*)pctx, wo, out);
}

// round 7
// speedup vs baseline: 1.5242x; 1.5242x over previous
#include <cuda_runtime.h>
#include <cuda_bf16.h>
#include <cstdint>

// Problem constants
#define EMB   1024
#define NH    16
#define HD    64
#define BATCH 2
#define SEQ   2048
#define MTOT  (BATCH*SEQ)   // 4096

// Scratch (device globals — no allocation allowed)
__device__ float g_q[(size_t)BATCH*NH*SEQ*HD];   // [B,H,S,D]
__device__ float g_k[(size_t)BATCH*NH*SEQ*HD];
__device__ float g_v[(size_t)BATCH*NH*SEQ*HD];
__device__ float g_ctx[(size_t)MTOT*EMB];        // [B,S,E]

// bf16 hi/lo staging for tensor-core GEMMs
__device__ __nv_bfloat16 g_xh[(size_t)MTOT*EMB];   // A hi  [m][k]
__device__ __nv_bfloat16 g_xl[(size_t)MTOT*EMB];   // A lo  [m][k]
__device__ __nv_bfloat16 g_wth[(size_t)EMB*EMB];   // W^T hi [n][k]
__device__ __nv_bfloat16 g_wtl[(size_t)EMB*EMB];   // W^T lo [n][k]

// ---------------------------------------------------------------------------
__device__ __forceinline__ uint32_t smem_u32(const void* p) {
    uint32_t a;
    asm("{ .reg .u64 t; cvta.to.shared.u64 t, %1; cvt.u32.u64 %0, t; }"
        : "=r"(a) : "l"(p));
    return a;
}

#define LDM4(r, addr)                                                          \
    asm volatile("ldmatrix.sync.aligned.m8n8.x4.shared.b16 {%0,%1,%2,%3}, [%4];" \
                 : "=r"((r)[0]), "=r"((r)[1]), "=r"((r)[2]), "=r"((r)[3])      \
                 : "r"(addr))

#define LDM2(r, addr)                                                          \
    asm volatile("ldmatrix.sync.aligned.m8n8.x2.shared.b16 {%0,%1}, [%2];"     \
                 : "=r"((r)[0]), "=r"((r)[1]) : "r"(addr))

#define MMA_BF16(d, a, b)                                                      \
    asm volatile("mma.sync.aligned.m16n8k16.row.col.f32.bf16.bf16.f32 "        \
                 "{%0,%1,%2,%3}, {%4,%5,%6,%7}, {%8,%9}, {%0,%1,%2,%3};"       \
                 : "+f"((d)[0]), "+f"((d)[1]), "+f"((d)[2]), "+f"((d)[3])      \
                 : "r"((a)[0]), "r"((a)[1]), "r"((a)[2]), "r"((a)[3]),         \
                   "r"((b)[0]), "r"((b)[1]))

#define CPASYNC16(sa, ga)                                                      \
    asm volatile("cp.async.cg.shared.global [%0], [%1], 16;"                   \
                 :: "r"(sa), "l"(ga))

// ---------------------------------------------------------------------------
// fp32 -> (hi, lo) bf16 split. One float4 per thread.
// ---------------------------------------------------------------------------
__global__ __launch_bounds__(256) void cvt_hilo(const float* __restrict__ X,
                                                __nv_bfloat16* __restrict__ H,
                                                __nv_bfloat16* __restrict__ L)
{
    int i = blockIdx.x * 256 + threadIdx.x;
    float4 v = reinterpret_cast<const float4*>(X)[i];
    __nv_bfloat162 h01 = __floats2bfloat162_rn(v.x, v.y);
    __nv_bfloat162 h23 = __floats2bfloat162_rn(v.z, v.w);
    float lx = v.x - __bfloat162float(h01.x);
    float ly = v.y - __bfloat162float(h01.y);
    float lz = v.z - __bfloat162float(h23.x);
    float lw = v.w - __bfloat162float(h23.y);
    __nv_bfloat162 l01 = __floats2bfloat162_rn(lx, ly);
    __nv_bfloat162 l23 = __floats2bfloat162_rn(lz, lw);
    uint2 hh, ll;
    hh.x = *reinterpret_cast<uint32_t*>(&h01);
    hh.y = *reinterpret_cast<uint32_t*>(&h23);
    ll.x = *reinterpret_cast<uint32_t*>(&l01);
    ll.y = *reinterpret_cast<uint32_t*>(&l23);
    reinterpret_cast<uint2*>(H)[i] = hh;
    reinterpret_cast<uint2*>(L)[i] = ll;
}

// ---------------------------------------------------------------------------
// Transpose + hi/lo split: W[k][n] fp32 -> WT_h/WT_l [n][k] bf16
// ---------------------------------------------------------------------------
__global__ __launch_bounds__(256) void transcvt_w(const float* __restrict__ W,
                                                  __nv_bfloat16* __restrict__ Th,
                                                  __nv_bfloat16* __restrict__ Tl)
{
    __shared__ float tile[32][33];
    int x = blockIdx.x * 32 + threadIdx.x;   // n
    int y = blockIdx.y * 32 + threadIdx.y;   // k
#pragma unroll
    for (int j = 0; j < 32; j += 8)
        tile[threadIdx.y + j][threadIdx.x] = W[(size_t)(y + j) * EMB + x];
    __syncthreads();
    int xo = blockIdx.y * 32 + threadIdx.x;  // k
    int yo = blockIdx.x * 32 + threadIdx.y;  // n
#pragma unroll
    for (int j = 0; j < 32; j += 8) {
        float v = tile[threadIdx.x][threadIdx.y + j];
        __nv_bfloat16 h = __float2bfloat16(v);
        float l = v - __bfloat162float(h);
        Th[(size_t)(yo + j) * EMB + xo] = h;
        Tl[(size_t)(yo + j) * EMB + xo] = __float2bfloat16(l);
    }
}

// ---------------------------------------------------------------------------
// mma.sync bf16x3 GEMM: C[4096,1024] = A @ W  (A,W pre-split hi/lo, W^T K-major)
// CTA 128x128, BK=64, 8 warps (2M x 4N, warp tile 64x32), double-buffered
// cp.async. smem tile rows padded to 144B for conflict-free ldmatrix.
// MODE 0: scatter to [B,H,S,D]; MODE 1: row-major.
// ---------------------------------------------------------------------------
#define TROW    144                    // bytes per smem tile row (128 + 16 pad)
#define TILE_B  (128 * TROW)           // 18432 B per tile
#define BUF_B   (4 * TILE_B)           // Ah,Al,Bh,Bl
#define GSMEM_BYTES (2 * BUF_B)        // 147456

template<int MODE>
__global__ __launch_bounds__(256) void gemm_mma(const __nv_bfloat16* __restrict__ Ah,
                                                const __nv_bfloat16* __restrict__ Al,
                                                const __nv_bfloat16* __restrict__ Bh,
                                                const __nv_bfloat16* __restrict__ Bl,
                                                float* __restrict__ Cout)
{
    extern __shared__ char smem[];
    const uint32_t sbase = smem_u32(smem);
    const int t  = threadIdx.x;
    const int l  = t & 31;
    const int w  = t >> 5;
    const int wm = w & 1;              // 0..1  (M)
    const int wn = w >> 1;             // 0..3  (N)
    const int m0 = blockIdx.y * 128;
    const int n0 = blockIdx.x * 128;

    float acc[4][4][4];
#pragma unroll
    for (int a = 0; a < 4; a++)
#pragma unroll
        for (int b = 0; b < 4; b++)
#pragma unroll
            for (int c = 0; c < 4; c++) acc[a][b][c] = 0.f;

    const char* gsrc[4] = {
        (const char*)(Ah + (size_t)m0 * EMB),
        (const char*)(Al + (size_t)m0 * EMB),
        (const char*)(Bh + (size_t)n0 * EMB),
        (const char*)(Bl + (size_t)n0 * EMB)
    };

    // Load one 64-K chunk: 4 tiles of 128 rows x 128B (+16B row pad in smem)
    auto load_chunk = [&](int kc, int buf) {
        uint32_t s0 = sbase + buf * BUF_B;
#pragma unroll
        for (int tile = 0; tile < 4; tile++) {
#pragma unroll
            for (int i = 0; i < 4; i++) {
                int e   = t + i * 256;         // 0..1023
                int row = e >> 3, seg = e & 7;
                uint32_t sa = s0 + tile * TILE_B + row * TROW + seg * 16;
                const char* ga = gsrc[tile] + (size_t)row * (EMB * 2)
                               + kc * 128 + seg * 16;
                CPASYNC16(sa, ga);
            }
        }
        asm volatile("cp.async.commit_group;" ::: "memory");
    };

    load_chunk(0, 0);

    for (int c = 0; c < 16; c++) {
        asm volatile("cp.async.wait_group 0;" ::: "memory");
        __syncthreads();
        if (c + 1 < 16) load_chunk(c + 1, (c + 1) & 1);

        uint32_t s0 = sbase + (c & 1) * BUF_B;
        // ldmatrix lane bases
        uint32_t aH = s0 + (wm * 64 + (l & 15)) * TROW + (l >> 4) * 16;
        uint32_t aL = aH + TILE_B;
        uint32_t bH = s0 + 2 * TILE_B + (wn * 32 + (l & 7)) * TROW
                    + ((l >> 3) & 1) * 16;
        uint32_t bL = bH + TILE_B;

#pragma unroll
        for (int ks = 0; ks < 4; ks++) {
            uint32_t ah[4][4], al[4][4], bh[4][2], bl[4][2];
#pragma unroll
            for (int ma = 0; ma < 4; ma++) {
                LDM4(ah[ma], aH + ma * 16 * TROW + ks * 32);
                LDM4(al[ma], aL + ma * 16 * TROW + ks * 32);
            }
#pragma unroll
            for (int nb = 0; nb < 4; nb++) {
                LDM2(bh[nb], bH + nb * 8 * TROW + ks * 32);
                LDM2(bl[nb], bL + nb * 8 * TROW + ks * 32);
            }
#pragma unroll
            for (int ma = 0; ma < 4; ma++)
#pragma unroll
                for (int nb = 0; nb < 4; nb++) {
                    MMA_BF16(acc[ma][nb], ah[ma], bh[nb]);
                    MMA_BF16(acc[ma][nb], al[ma], bh[nb]);
                    MMA_BF16(acc[ma][nb], ah[ma], bl[nb]);
                }
        }
    }

    // Epilogue: c frag -> global. rows = groupID(+8), cols = 2*tig + {0,1}
#pragma unroll
    for (int ma = 0; ma < 4; ma++) {
#pragma unroll
        for (int nb = 0; nb < 4; nb++) {
            int n = n0 + wn * 32 + nb * 8 + (l & 3) * 2;
#pragma unroll
            for (int half = 0; half < 2; half++) {
                int m = m0 + wm * 64 + ma * 16 + (l >> 2) + half * 8;
                float2 v = make_float2(acc[ma][nb][half * 2],
                                       acc[ma][nb][half * 2 + 1]);
                if (MODE == 0) {
                    int b = m >> 11, s = m & 2047;
                    int h = n >> 6,  d = n & 63;
                    *reinterpret_cast<float2*>(
                        Cout + (((size_t)(b * NH + h) * SEQ + s) * HD + d)) = v;
                } else {
                    *reinterpret_cast<float2*>(Cout + (size_t)m * EMB + n) = v;
                }
            }
        }
    }
}

// ---------------------------------------------------------------------------
// Flash attention, causal. BM=BN=64, D=64, 128 threads.
// Tiles: 64 x 64 floats, 256B rows, XOR-swizzled 16B blocks (conflict-free
// float4 LDS). Online softmax in registers, P staged via smem.
// ---------------------------------------------------------------------------
__device__ __forceinline__ int swz(int row, int col) {   // word index
    return (row * 64 + col) ^ (((row >> 3) & 7) << 2);
}

#define ATTN_SMEM (4 * 64 * 64 * 4)   // 65536 B

__global__ __launch_bounds__(128) void attn_kernel()
{
    extern __shared__ float sm[];
    float* Qs = sm;                 // 64 x 64 swizzled
    float* Ks = sm + 4096;
    float* Vs = sm + 8192;
    float* Ps = sm + 12288;

    const int t  = threadIdx.x;
    const int tx = t & 7;           // 8 cols each
    const int ty = t >> 3;          // 4 rows each
    const int bh = blockIdx.y;
    const int rb = (gridDim.x - 1) - blockIdx.x;   // heavy blocks first
    const int m0 = rb * 64;

    // Load Q tile
    const float* Qg = g_q + ((size_t)bh * SEQ + m0) * HD;
#pragma unroll
    for (int f = t; f < 1024; f += 128) {
        int row = f >> 4;
        int c4  = (f & 15) << 2;
        float4 v = reinterpret_cast<const float4*>(Qg)[f];
        *reinterpret_cast<float4*>(&Qs[swz(row, c4)]) = v;
    }

    float mi[4], li[4], o[4][8];
#pragma unroll
    for (int i = 0; i < 4; i++) {
        mi[i] = -1e30f;
        li[i] = 0.f;
#pragma unroll
        for (int j = 0; j < 8; j++) o[i][j] = 0.f;
    }

    for (int jb = 0; jb <= rb; jb++) {
        __syncthreads();

        const float* Kg = g_k + ((size_t)bh * SEQ + jb * 64) * HD;
        const float* Vg = g_v + ((size_t)bh * SEQ + jb * 64) * HD;
#pragma unroll
        for (int f = t; f < 1024; f += 128) {
            int row = f >> 4;
            int c4  = (f & 15) << 2;
            float4 v = reinterpret_cast<const float4*>(Kg)[f];
            *reinterpret_cast<float4*>(&Ks[swz(row, c4)]) = v;
            float4 u = reinterpret_cast<const float4*>(Vg)[f];
            *reinterpret_cast<float4*>(&Vs[swz(row, c4)]) = u;
        }
        __syncthreads();

        // S = Q @ K^T : float4 over k
        float c[4][8];
#pragma unroll
        for (int i = 0; i < 4; i++)
#pragma unroll
            for (int j = 0; j < 8; j++) c[i][j] = 0.f;

#pragma unroll 4
        for (int k4 = 0; k4 < 64; k4 += 4) {
            float4 q4[4], kv[8];
#pragma unroll
            for (int i = 0; i < 4; i++)
                q4[i] = *reinterpret_cast<float4*>(&Qs[swz(ty * 4 + i, k4)]);
#pragma unroll
            for (int j = 0; j < 8; j++)
                kv[j] = *reinterpret_cast<float4*>(&Ks[swz(tx * 8 + j, k4)]);
#pragma unroll
            for (int i = 0; i < 4; i++)
#pragma unroll
                for (int j = 0; j < 8; j++) {
                    c[i][j] = fmaf(q4[i].x, kv[j].x, c[i][j]);
                    c[i][j] = fmaf(q4[i].y, kv[j].y, c[i][j]);
                    c[i][j] = fmaf(q4[i].z, kv[j].z, c[i][j]);
                    c[i][j] = fmaf(q4[i].w, kv[j].w, c[i][j]);
                }
        }

        // scale + causal mask + online softmax
        const bool diag = (jb == rb);
#pragma unroll
        for (int i = 0; i < 4; i++) {
            int ig = m0 + ty * 4 + i;
            float rmax = -1e30f;
#pragma unroll
            for (int j = 0; j < 8; j++) {
                float s = c[i][j] * 0.125f;   // 1/sqrt(64)
                if (diag && (jb * 64 + tx * 8 + j) > ig) s = -1e30f;
                c[i][j] = s;
                rmax = fmaxf(rmax, s);
            }
            rmax = fmaxf(rmax, __shfl_xor_sync(0xffffffffu, rmax, 1));
            rmax = fmaxf(rmax, __shfl_xor_sync(0xffffffffu, rmax, 2));
            rmax = fmaxf(rmax, __shfl_xor_sync(0xffffffffu, rmax, 4));
            float mnew  = fmaxf(mi[i], rmax);
            float alpha = __expf(mi[i] - mnew);
            float rsum  = 0.f;
#pragma unroll
            for (int j = 0; j < 8; j++) {
                float p = __expf(c[i][j] - mnew);
                c[i][j] = p;
                rsum += p;
            }
            rsum += __shfl_xor_sync(0xffffffffu, rsum, 1);
            rsum += __shfl_xor_sync(0xffffffffu, rsum, 2);
            rsum += __shfl_xor_sync(0xffffffffu, rsum, 4);
            li[i] = li[i] * alpha + rsum;
            mi[i] = mnew;
#pragma unroll
            for (int j = 0; j < 8; j++) o[i][j] *= alpha;
        }

        // stage P, then O += P @ V
#pragma unroll
        for (int i = 0; i < 4; i++)
#pragma unroll
            for (int j = 0; j < 8; j++)
                Ps[swz(ty * 4 + i, tx * 8 + j)] = c[i][j];
        __syncthreads();

#pragma unroll 4
        for (int k4 = 0; k4 < 64; k4 += 4) {
            float pa[4][4];
#pragma unroll
            for (int i = 0; i < 4; i++) {
                float4 tp = *reinterpret_cast<float4*>(&Ps[swz(ty * 4 + i, k4)]);
                pa[i][0] = tp.x; pa[i][1] = tp.y;
                pa[i][2] = tp.z; pa[i][3] = tp.w;
            }
#pragma unroll
            for (int kk = 0; kk < 4; kk++) {
                float4 va = *reinterpret_cast<float4*>(&Vs[swz(k4 + kk, tx * 8)]);
                float4 vb = *reinterpret_cast<float4*>(&Vs[swz(k4 + kk, tx * 8 + 4)]);
#pragma unroll
                for (int i = 0; i < 4; i++) {
                    float p = pa[i][kk];
                    o[i][0] = fmaf(p, va.x, o[i][0]);
                    o[i][1] = fmaf(p, va.y, o[i][1]);
                    o[i][2] = fmaf(p, va.z, o[i][2]);
                    o[i][3] = fmaf(p, va.w, o[i][3]);
                    o[i][4] = fmaf(p, vb.x, o[i][4]);
                    o[i][5] = fmaf(p, vb.y, o[i][5]);
                    o[i][6] = fmaf(p, vb.z, o[i][6]);
                    o[i][7] = fmaf(p, vb.w, o[i][7]);
                }
            }
        }

        // P consumed; loop-top __syncthreads covers reuse of Ps/Ks/Vs
    }

    // Epilogue: normalize and write to g_ctx [B,S,E]
    const int b = bh >> 4, h = bh & 15;
#pragma unroll
    for (int i = 0; i < 4; i++) {
        float inv = 1.0f / li[i];
        int s = m0 + ty * 4 + i;
        float* dst = g_ctx + ((size_t)(b * SEQ + s)) * EMB + h * HD + tx * 8;
        float4 v0 = make_float4(o[i][0] * inv, o[i][1] * inv,
                                o[i][2] * inv, o[i][3] * inv);
        float4 v1 = make_float4(o[i][4] * inv, o[i][5] * inv,
                                o[i][6] * inv, o[i][7] * inv);
        *reinterpret_cast<float4*>(dst)     = v0;
        *reinterpret_cast<float4*>(dst + 4) = v1;
    }
}

// ---------------------------------------------------------------------------
extern "C" void kernel_launch(void* const* d_in, const int* in_sizes, int n_in,
                              void* d_out, int out_size)
{
    const float* x  = (const float*)d_in[0];
    const float* wq = (const float*)d_in[1];
    const float* wk = (const float*)d_in[2];
    const float* wv = (const float*)d_in[3];
    const float* wo = (const float*)d_in[4];
    float* out = (float*)d_out;

    void *pq, *pk, *pv, *pctx, *pxh, *pxl, *pwh, *pwl;
    cudaGetSymbolAddress(&pq,   g_q);
    cudaGetSymbolAddress(&pk,   g_k);
    cudaGetSymbolAddress(&pv,   g_v);
    cudaGetSymbolAddress(&pctx, g_ctx);
    cudaGetSymbolAddress(&pxh,  g_xh);
    cudaGetSymbolAddress(&pxl,  g_xl);
    cudaGetSymbolAddress(&pwh,  g_wth);
    cudaGetSymbolAddress(&pwl,  g_wtl);

    __nv_bfloat16* xh = (__nv_bfloat16*)pxh;
    __nv_bfloat16* xl = (__nv_bfloat16*)pxl;
    __nv_bfloat16* wh = (__nv_bfloat16*)pwh;
    __nv_bfloat16* wl = (__nv_bfloat16*)pwl;

    cudaFuncSetAttribute(attn_kernel,
                         cudaFuncAttributeMaxDynamicSharedMemorySize, ATTN_SMEM);
    cudaFuncSetAttribute(gemm_mma<0>,
                         cudaFuncAttributeMaxDynamicSharedMemorySize, GSMEM_BYTES);
    cudaFuncSetAttribute(gemm_mma<1>,
                         cudaFuncAttributeMaxDynamicSharedMemorySize, GSMEM_BYTES);

    dim3 gw(32, 32), bw(32, 8);                 // W transpose-convert
    dim3 gg(EMB / 128, MTOT / 128);             // (8, 32) GEMM grid

    // x -> hi/lo bf16
    cvt_hilo<<<MTOT * EMB / 4 / 256, 256>>>(x, xh, xl);

    // Q, K, V projections (tensor pipe, scatter to [B,H,S,D])
    transcvt_w<<<gw, bw>>>(wq, wh, wl);
    gemm_mma<0><<<gg, 256, GSMEM_BYTES>>>(xh, xl, wh, wl, (float*)pq);
    transcvt_w<<<gw, bw>>>(wk, wh, wl);
    gemm_mma<0><<<gg, 256, GSMEM_BYTES>>>(xh, xl, wh, wl, (float*)pk);
    transcvt_w<<<gw, bw>>>(wv, wh, wl);
    gemm_mma<0><<<gg, 256, GSMEM_BYTES>>>(xh, xl, wh, wl, (float*)pv);

    // Attention
    attn_kernel<<<dim3(SEQ / 64, BATCH * NH), 128, ATTN_SMEM>>>();

    // Out projection (reuse xh/xl buffers for ctx hi/lo)
    cvt_hilo<<<MTOT * EMB / 4 / 256, 256>>>((const float*)pctx, xh, xl);
    transcvt_w<<<gw, bw>>>(wo, wh, wl);
    gemm_mma<1><<<gg, 256, GSMEM_BYTES>>>(xh, xl, wh, wl, out);
}

// round 8
// speedup vs baseline: 3.0497x; 2.0008x over previous
#include <cuda_runtime.h>
#include <cuda_bf16.h>
#include <cstdint>

// Problem constants
#define EMB   1024
#define NH    16
#define HD    64
#define BATCH 2
#define SEQ   2048
#define MTOT  (BATCH*SEQ)   // 4096

// Scratch (device globals — no allocation allowed)
__device__ float g_ctx[(size_t)MTOT*EMB];        // [B,S,E]

// bf16 hi/lo staging
__device__ __nv_bfloat16 g_xh[(size_t)MTOT*EMB];   // A hi  [m][k]
__device__ __nv_bfloat16 g_xl[(size_t)MTOT*EMB];   // A lo  [m][k]
__device__ __nv_bfloat16 g_wth[(size_t)EMB*EMB];   // W^T hi [n][k]
__device__ __nv_bfloat16 g_wtl[(size_t)EMB*EMB];   // W^T lo [n][k]

// Q/K/V in bf16 hi/lo, [B,H,S,D]
#define QKV_ELEMS ((size_t)BATCH*NH*SEQ*HD)
__device__ __nv_bfloat16 g_qh[QKV_ELEMS], g_ql[QKV_ELEMS];
__device__ __nv_bfloat16 g_kh[QKV_ELEMS], g_kl[QKV_ELEMS];
__device__ __nv_bfloat16 g_vh[QKV_ELEMS], g_vl[QKV_ELEMS];

// ---------------------------------------------------------------------------
__device__ __forceinline__ uint32_t smem_u32(const void* p) {
    uint32_t a;
    asm("{ .reg .u64 t; cvta.to.shared.u64 t, %1; cvt.u32.u64 %0, t; }"
        : "=r"(a) : "l"(p));
    return a;
}

#define LDM4(r, addr)                                                          \
    asm volatile("ldmatrix.sync.aligned.m8n8.x4.shared.b16 {%0,%1,%2,%3}, [%4];" \
                 : "=r"((r)[0]), "=r"((r)[1]), "=r"((r)[2]), "=r"((r)[3])      \
                 : "r"(addr))

#define LDM2(r, addr)                                                          \
    asm volatile("ldmatrix.sync.aligned.m8n8.x2.shared.b16 {%0,%1}, [%2];"     \
                 : "=r"((r)[0]), "=r"((r)[1]) : "r"(addr))

#define LDM2T(r, addr)                                                         \
    asm volatile("ldmatrix.sync.aligned.m8n8.x2.trans.shared.b16 {%0,%1}, [%2];" \
                 : "=r"((r)[0]), "=r"((r)[1]) : "r"(addr))

#define MMA_BF16(d, a, b)                                                      \
    asm volatile("mma.sync.aligned.m16n8k16.row.col.f32.bf16.bf16.f32 "        \
                 "{%0,%1,%2,%3}, {%4,%5,%6,%7}, {%8,%9}, {%0,%1,%2,%3};"       \
                 : "+f"((d)[0]), "+f"((d)[1]), "+f"((d)[2]), "+f"((d)[3])      \
                 : "r"((a)[0]), "r"((a)[1]), "r"((a)[2]), "r"((a)[3]),         \
                   "r"((b)[0]), "r"((b)[1]))

#define CPASYNC16(sa, ga)                                                      \
    asm volatile("cp.async.cg.shared.global [%0], [%1], 16;"                   \
                 :: "r"(sa), "l"(ga))

__device__ __forceinline__ uint32_t pack_hilo(float x, float y, uint32_t& lo) {
    __nv_bfloat162 h = __floats2bfloat162_rn(x, y);
    float rx = x - __bfloat162float(h.x);
    float ry = y - __bfloat162float(h.y);
    __nv_bfloat162 l2 = __floats2bfloat162_rn(rx, ry);
    lo = *reinterpret_cast<uint32_t*>(&l2);
    return *reinterpret_cast<uint32_t*>(&h);
}

// ---------------------------------------------------------------------------
// fp32 -> (hi, lo) bf16 split. One float4 per thread.
// ---------------------------------------------------------------------------
__global__ __launch_bounds__(256) void cvt_hilo(const float* __restrict__ X,
                                                __nv_bfloat16* __restrict__ H,
                                                __nv_bfloat16* __restrict__ L)
{
    int i = blockIdx.x * 256 + threadIdx.x;
    float4 v = reinterpret_cast<const float4*>(X)[i];
    uint2 hh, ll;
    hh.x = pack_hilo(v.x, v.y, ll.x);
    hh.y = pack_hilo(v.z, v.w, ll.y);
    reinterpret_cast<uint2*>(H)[i] = hh;
    reinterpret_cast<uint2*>(L)[i] = ll;
}

// ---------------------------------------------------------------------------
// Transpose + hi/lo split: W[k][n] fp32 -> WT_h/WT_l [n][k] bf16
// ---------------------------------------------------------------------------
__global__ __launch_bounds__(256) void transcvt_w(const float* __restrict__ W,
                                                  __nv_bfloat16* __restrict__ Th,
                                                  __nv_bfloat16* __restrict__ Tl)
{
    __shared__ float tile[32][33];
    int x = blockIdx.x * 32 + threadIdx.x;
    int y = blockIdx.y * 32 + threadIdx.y;
#pragma unroll
    for (int j = 0; j < 32; j += 8)
        tile[threadIdx.y + j][threadIdx.x] = W[(size_t)(y + j) * EMB + x];
    __syncthreads();
    int xo = blockIdx.y * 32 + threadIdx.x;
    int yo = blockIdx.x * 32 + threadIdx.y;
#pragma unroll
    for (int j = 0; j < 32; j += 8) {
        float v = tile[threadIdx.x][threadIdx.y + j];
        __nv_bfloat16 h = __float2bfloat16(v);
        float l = v - __bfloat162float(h);
        Th[(size_t)(yo + j) * EMB + xo] = h;
        Tl[(size_t)(yo + j) * EMB + xo] = __float2bfloat16(l);
    }
}

// ---------------------------------------------------------------------------
// mma.sync bf16x3 GEMM (validated R7). CTA 128x128, BK=64, 8 warps.
// MODE 0: write bf16 hi/lo scattered to [B,H,S,D]; MODE 1: fp32 row-major.
// ---------------------------------------------------------------------------
#define TROW    144
#define TILE_B  (128 * TROW)
#define BUF_B   (4 * TILE_B)
#define GSMEM_BYTES (2 * BUF_B)        // 147456

template<int MODE>
__global__ __launch_bounds__(256) void gemm_mma(const __nv_bfloat16* __restrict__ Ah,
                                                const __nv_bfloat16* __restrict__ Al,
                                                const __nv_bfloat16* __restrict__ Bh,
                                                const __nv_bfloat16* __restrict__ Bl,
                                                float* __restrict__ Cout,
                                                __nv_bfloat16* __restrict__ Oh,
                                                __nv_bfloat16* __restrict__ Ol)
{
    extern __shared__ char smem[];
    const uint32_t sbase = smem_u32(smem);
    const int t  = threadIdx.x;
    const int l  = t & 31;
    const int w  = t >> 5;
    const int wm = w & 1;
    const int wn = w >> 1;
    const int m0 = blockIdx.y * 128;
    const int n0 = blockIdx.x * 128;

    float acc[4][4][4];
#pragma unroll
    for (int a = 0; a < 4; a++)
#pragma unroll
        for (int b = 0; b < 4; b++)
#pragma unroll
            for (int c = 0; c < 4; c++) acc[a][b][c] = 0.f;

    const char* gsrc[4] = {
        (const char*)(Ah + (size_t)m0 * EMB),
        (const char*)(Al + (size_t)m0 * EMB),
        (const char*)(Bh + (size_t)n0 * EMB),
        (const char*)(Bl + (size_t)n0 * EMB)
    };

    auto load_chunk = [&](int kc, int buf) {
        uint32_t s0 = sbase + buf * BUF_B;
#pragma unroll
        for (int tile = 0; tile < 4; tile++) {
#pragma unroll
            for (int i = 0; i < 4; i++) {
                int e   = t + i * 256;
                int row = e >> 3, seg = e & 7;
                uint32_t sa = s0 + tile * TILE_B + row * TROW + seg * 16;
                const char* ga = gsrc[tile] + (size_t)row * (EMB * 2)
                               + kc * 128 + seg * 16;
                CPASYNC16(sa, ga);
            }
        }
        asm volatile("cp.async.commit_group;" ::: "memory");
    };

    load_chunk(0, 0);

    for (int c = 0; c < 16; c++) {
        asm volatile("cp.async.wait_group 0;" ::: "memory");
        __syncthreads();
        if (c + 1 < 16) load_chunk(c + 1, (c + 1) & 1);

        uint32_t s0 = sbase + (c & 1) * BUF_B;
        uint32_t aH = s0 + (wm * 64 + (l & 15)) * TROW + (l >> 4) * 16;
        uint32_t aL = aH + TILE_B;
        uint32_t bH = s0 + 2 * TILE_B + (wn * 32 + (l & 7)) * TROW
                    + ((l >> 3) & 1) * 16;
        uint32_t bL = bH + TILE_B;

#pragma unroll
        for (int ks = 0; ks < 4; ks++) {
            uint32_t ah[4][4], al[4][4], bh[4][2], bl[4][2];
#pragma unroll
            for (int ma = 0; ma < 4; ma++) {
                LDM4(ah[ma], aH + ma * 16 * TROW + ks * 32);
                LDM4(al[ma], aL + ma * 16 * TROW + ks * 32);
            }
#pragma unroll
            for (int nb = 0; nb < 4; nb++) {
                LDM2(bh[nb], bH + nb * 8 * TROW + ks * 32);
                LDM2(bl[nb], bL + nb * 8 * TROW + ks * 32);
            }
#pragma unroll
            for (int ma = 0; ma < 4; ma++)
#pragma unroll
                for (int nb = 0; nb < 4; nb++) {
                    MMA_BF16(acc[ma][nb], ah[ma], bh[nb]);
                    MMA_BF16(acc[ma][nb], al[ma], bh[nb]);
                    MMA_BF16(acc[ma][nb], ah[ma], bl[nb]);
                }
        }
    }

#pragma unroll
    for (int ma = 0; ma < 4; ma++) {
#pragma unroll
        for (int nb = 0; nb < 4; nb++) {
            int n = n0 + wn * 32 + nb * 8 + (l & 3) * 2;
#pragma unroll
            for (int half = 0; half < 2; half++) {
                int m = m0 + wm * 64 + ma * 16 + (l >> 2) + half * 8;
                float vx = acc[ma][nb][half * 2];
                float vy = acc[ma][nb][half * 2 + 1];
                if (MODE == 0) {
                    int b = m >> 11, s = m & 2047;
                    int h = n >> 6,  d = n & 63;
                    size_t idx = ((size_t)(b * NH + h) * SEQ + s) * HD + d;
                    uint32_t lo, hi = pack_hilo(vx, vy, lo);
                    *reinterpret_cast<uint32_t*>(Oh + idx) = hi;
                    *reinterpret_cast<uint32_t*>(Ol + idx) = lo;
                } else {
                    *reinterpret_cast<float2*>(Cout + (size_t)m * EMB + n) =
                        make_float2(vx, vy);
                }
            }
        }
    }
}

// ---------------------------------------------------------------------------
// Flash attention, causal, tensor-core (mma.sync bf16x3), FA2 style.
// BM=64 (4 warps x m16), BN=64, D=64. 128 threads.
// smem: Qh/Ql (16KB) + double-buffered {Kh,Kl,Vh,Vl} (2 x 32KB) = 80KB.
// Tile rows: 64 x 128B, XOR-seg swizzle (seg ^ (row&7)).
// ---------------------------------------------------------------------------
#define ASW(base, row, seg) ((base) + (uint32_t)(row) * 128u +                 \
                             (uint32_t)(((seg) ^ ((row) & 7)) * 16))
#define ATTN_SMEM (16384 + 2 * 32768)   // 81920

__global__ __launch_bounds__(128) void attn_mma()
{
    extern __shared__ char smc[];
    const uint32_t sb = smem_u32(smc);
    const int t = threadIdx.x, l = t & 31, w = t >> 5;
    const int bh = blockIdx.y;
    const int rb = (gridDim.x - 1) - blockIdx.x;   // heavy blocks first
    const int m0 = rb * 64;

    const uint32_t QH = sb, QL = sb + 8192;
    const uint32_t KVB = sb + 16384;               // + buf*32768

    // Preload Q hi/lo tile (group 1)
    {
        size_t off = ((size_t)bh * SEQ + m0) * HD;
        const char* gh = (const char*)(g_qh + off);
        const char* gl = (const char*)(g_ql + off);
#pragma unroll
        for (int i = 0; i < 4; i++) {
            int e = t + i * 128, row = e >> 3, seg = e & 7;
            int go = row * 128 + seg * 16;
            CPASYNC16(ASW(QH, row, seg), gh + go);
            CPASYNC16(ASW(QL, row, seg), gl + go);
        }
        asm volatile("cp.async.commit_group;" ::: "memory");
    }

    auto load_kv = [&](int jb, int buf) {
        uint32_t base = KVB + buf * 32768;
        size_t off = ((size_t)bh * SEQ + jb * 64) * HD;
        const char* s0 = (const char*)(g_kh + off);
        const char* s1 = (const char*)(g_kl + off);
        const char* s2 = (const char*)(g_vh + off);
        const char* s3 = (const char*)(g_vl + off);
#pragma unroll
        for (int i = 0; i < 4; i++) {
            int e = t + i * 128, row = e >> 3, seg = e & 7;
            int go = row * 128 + seg * 16;
            CPASYNC16(ASW(base,         row, seg), s0 + go);
            CPASYNC16(ASW(base +  8192, row, seg), s1 + go);
            CPASYNC16(ASW(base + 16384, row, seg), s2 + go);
            CPASYNC16(ASW(base + 24576, row, seg), s3 + go);
        }
        asm volatile("cp.async.commit_group;" ::: "memory");
    };

    load_kv(0, 0);
    asm volatile("cp.async.wait_group 0;" ::: "memory");
    __syncthreads();

    // Q A-fragments (hi/lo), row = w*16 + (l&15), k-halves by l>>4
    uint32_t qh[4][4], ql[4][4];
    {
        int row = w * 16 + (l & 15);
#pragma unroll
        for (int kt = 0; kt < 4; kt++) {
            LDM4(qh[kt], ASW(QH, row, kt * 2 + (l >> 4)));
            LDM4(ql[kt], ASW(QL, row, kt * 2 + (l >> 4)));
        }
    }

    float oacc[8][4];
#pragma unroll
    for (int d = 0; d < 8; d++)
#pragma unroll
        for (int j = 0; j < 4; j++) oacc[d][j] = 0.f;
    float mi0 = -1e30f, mi1 = -1e30f, li0 = 0.f, li1 = 0.f;

    const int r0 = m0 + w * 16 + (l >> 2);    // global row (c0,c1); +8 for c2,c3

    for (int jb = 0; jb <= rb; jb++) {
        const int buf = jb & 1;
        if (jb > 0) {
            asm volatile("cp.async.wait_group 0;" ::: "memory");
            __syncthreads();
        }
        if (jb < rb) load_kv(jb + 1, buf ^ 1);

        const uint32_t Kb = KVB + buf * 32768;
        const uint32_t Vb = Kb + 16384;

        // S = Q @ K^T (bf16x3)
        float sacc[8][4];
#pragma unroll
        for (int nt = 0; nt < 8; nt++)
#pragma unroll
            for (int j = 0; j < 4; j++) sacc[nt][j] = 0.f;

#pragma unroll
        for (int nt = 0; nt < 8; nt++) {
            int row = nt * 8 + (l & 7);
#pragma unroll
            for (int ks = 0; ks < 4; ks++) {
                uint32_t kh[2], kl[2];
                int seg = ks * 2 + ((l >> 3) & 1);
                LDM2(kh, ASW(Kb,        row, seg));
                LDM2(kl, ASW(Kb + 8192, row, seg));
                MMA_BF16(sacc[nt], qh[ks], kh);
                MMA_BF16(sacc[nt], ql[ks], kh);
                MMA_BF16(sacc[nt], qh[ks], kl);
            }
        }

        // scale + causal mask + online softmax
        const bool diag = (jb == rb);
        float rmax0 = -1e30f, rmax1 = -1e30f;
#pragma unroll
        for (int nt = 0; nt < 8; nt++) {
            int cj = jb * 64 + nt * 8 + 2 * (l & 3);
            float s0 = sacc[nt][0] * 0.125f;
            float s1 = sacc[nt][1] * 0.125f;
            float s2 = sacc[nt][2] * 0.125f;
            float s3 = sacc[nt][3] * 0.125f;
            if (diag) {
                if (cj     > r0)     s0 = -1e30f;
                if (cj + 1 > r0)     s1 = -1e30f;
                if (cj     > r0 + 8) s2 = -1e30f;
                if (cj + 1 > r0 + 8) s3 = -1e30f;
            }
            sacc[nt][0] = s0; sacc[nt][1] = s1;
            sacc[nt][2] = s2; sacc[nt][3] = s3;
            rmax0 = fmaxf(rmax0, fmaxf(s0, s1));
            rmax1 = fmaxf(rmax1, fmaxf(s2, s3));
        }
        rmax0 = fmaxf(rmax0, __shfl_xor_sync(0xffffffffu, rmax0, 1));
        rmax0 = fmaxf(rmax0, __shfl_xor_sync(0xffffffffu, rmax0, 2));
        rmax1 = fmaxf(rmax1, __shfl_xor_sync(0xffffffffu, rmax1, 1));
        rmax1 = fmaxf(rmax1, __shfl_xor_sync(0xffffffffu, rmax1, 2));

        float mn0 = fmaxf(mi0, rmax0), mn1 = fmaxf(mi1, rmax1);
        float a0 = __expf(mi0 - mn0),  a1 = __expf(mi1 - mn1);
        float sum0 = 0.f, sum1 = 0.f;
#pragma unroll
        for (int nt = 0; nt < 8; nt++) {
            float p0 = __expf(sacc[nt][0] - mn0);
            float p1 = __expf(sacc[nt][1] - mn0);
            float p2 = __expf(sacc[nt][2] - mn1);
            float p3 = __expf(sacc[nt][3] - mn1);
            sacc[nt][0] = p0; sacc[nt][1] = p1;
            sacc[nt][2] = p2; sacc[nt][3] = p3;
            sum0 += p0 + p1; sum1 += p2 + p3;
        }
        sum0 += __shfl_xor_sync(0xffffffffu, sum0, 1);
        sum0 += __shfl_xor_sync(0xffffffffu, sum0, 2);
        sum1 += __shfl_xor_sync(0xffffffffu, sum1, 1);
        sum1 += __shfl_xor_sync(0xffffffffu, sum1, 2);
        li0 = li0 * a0 + sum0;  mi0 = mn0;
        li1 = li1 * a1 + sum1;  mi1 = mn1;
#pragma unroll
        for (int d = 0; d < 8; d++) {
            oacc[d][0] *= a0; oacc[d][1] *= a0;
            oacc[d][2] *= a1; oacc[d][3] *= a1;
        }

        // O += P @ V (bf16x3). S-frag pair (2 n-tiles) == A-frag for k16.
#pragma unroll
        for (int ks = 0; ks < 4; ks++) {
            uint32_t ph[4], pl[4];
            ph[0] = pack_hilo(sacc[2*ks][0],   sacc[2*ks][1],   pl[0]);
            ph[1] = pack_hilo(sacc[2*ks][2],   sacc[2*ks][3],   pl[1]);
            ph[2] = pack_hilo(sacc[2*ks+1][0], sacc[2*ks+1][1], pl[2]);
            ph[3] = pack_hilo(sacc[2*ks+1][2], sacc[2*ks+1][3], pl[3]);
            int row = ks * 16 + (l & 7) + 8 * ((l >> 3) & 1);
#pragma unroll
            for (int dt = 0; dt < 8; dt++) {
                uint32_t vh[2], vl[2];
                LDM2T(vh, ASW(Vb,        row, dt));
                LDM2T(vl, ASW(Vb + 8192, row, dt));
                MMA_BF16(oacc[dt], ph, vh);
                MMA_BF16(oacc[dt], pl, vh);
                MMA_BF16(oacc[dt], ph, vl);
            }
        }
    }

    // Epilogue: normalize, write g_ctx [B,S,E] fp32
    {
        float inv0 = 1.f / li0, inv1 = 1.f / li1;
        int b = bh >> 4, h = bh & 15;
        int row = m0 + w * 16 + (l >> 2);
        float* base = g_ctx + ((size_t)(b * SEQ) + row) * EMB + h * 64 + 2 * (l & 3);
#pragma unroll
        for (int dt = 0; dt < 8; dt++) {
            *reinterpret_cast<float2*>(base + dt * 8) =
                make_float2(oacc[dt][0] * inv0, oacc[dt][1] * inv0);
            *reinterpret_cast<float2*>(base + 8 * EMB + dt * 8) =
                make_float2(oacc[dt][2] * inv1, oacc[dt][3] * inv1);
        }
    }
}

// ---------------------------------------------------------------------------
extern "C" void kernel_launch(void* const* d_in, const int* in_sizes, int n_in,
                              void* d_out, int out_size)
{
    const float* x  = (const float*)d_in[0];
    const float* wq = (const float*)d_in[1];
    const float* wk = (const float*)d_in[2];
    const float* wv = (const float*)d_in[3];
    const float* wo = (const float*)d_in[4];
    float* out = (float*)d_out;

    void *pctx, *pxh, *pxl, *pwh, *pwl;
    void *pqh, *pql, *pkh, *pkl, *pvh, *pvl;
    cudaGetSymbolAddress(&pctx, g_ctx);
    cudaGetSymbolAddress(&pxh,  g_xh);
    cudaGetSymbolAddress(&pxl,  g_xl);
    cudaGetSymbolAddress(&pwh,  g_wth);
    cudaGetSymbolAddress(&pwl,  g_wtl);
    cudaGetSymbolAddress(&pqh,  g_qh);
    cudaGetSymbolAddress(&pql,  g_ql);
    cudaGetSymbolAddress(&pkh,  g_kh);
    cudaGetSymbolAddress(&pkl,  g_kl);
    cudaGetSymbolAddress(&pvh,  g_vh);
    cudaGetSymbolAddress(&pvl,  g_vl);

    __nv_bfloat16* xh = (__nv_bfloat16*)pxh;
    __nv_bfloat16* xl = (__nv_bfloat16*)pxl;
    __nv_bfloat16* wh = (__nv_bfloat16*)pwh;
    __nv_bfloat16* wl = (__nv_bfloat16*)pwl;

    cudaFuncSetAttribute(attn_mma,
                         cudaFuncAttributeMaxDynamicSharedMemorySize, ATTN_SMEM);
    cudaFuncSetAttribute(gemm_mma<0>,
                         cudaFuncAttributeMaxDynamicSharedMemorySize, GSMEM_BYTES);
    cudaFuncSetAttribute(gemm_mma<1>,
                         cudaFuncAttributeMaxDynamicSharedMemorySize, GSMEM_BYTES);

    dim3 gw(32, 32), bw(32, 8);
    dim3 gg(EMB / 128, MTOT / 128);

    cvt_hilo<<<MTOT * EMB / 4 / 256, 256>>>(x, xh, xl);

    transcvt_w<<<gw, bw>>>(wq, wh, wl);
    gemm_mma<0><<<gg, 256, GSMEM_BYTES>>>(xh, xl, wh, wl, nullptr,
                                          (__nv_bfloat16*)pqh, (__nv_bfloat16*)pql);
    transcvt_w<<<gw, bw>>>(wk, wh, wl);
    gemm_mma<0><<<gg, 256, GSMEM_BYTES>>>(xh, xl, wh, wl, nullptr,
                                          (__nv_bfloat16*)pkh, (__nv_bfloat16*)pkl);
    transcvt_w<<<gw, bw>>>(wv, wh, wl);
    gemm_mma<0><<<gg, 256, GSMEM_BYTES>>>(xh, xl, wh, wl, nullptr,
                                          (__nv_bfloat16*)pvh, (__nv_bfloat16*)pvl);

    attn_mma<<<dim3(SEQ / 64, BATCH * NH), 128, ATTN_SMEM>>>();

    cvt_hilo<<<MTOT * EMB / 4 / 256, 256>>>((const float*)pctx, xh, xl);
    transcvt_w<<<gw, bw>>>(wo, wh, wl);
    gemm_mma<1><<<gg, 256, GSMEM_BYTES>>>(xh, xl, wh, wl, out, nullptr, nullptr);
}

// round 11
// speedup vs baseline: 4.4844x; 1.4704x over previous
#include <cuda_runtime.h>
#include <cuda_fp16.h>
#include <cstdint>

// Problem constants
#define EMB   1024
#define NH    16
#define HD    64
#define BATCH 2
#define SEQ   2048
#define MTOT  (BATCH*SEQ)   // 4096

// Scratch (device globals — no allocation allowed). All fp16.
__device__ __half g_xh[(size_t)MTOT*EMB];      // x hi  [m][k]
__device__ __half g_xl[(size_t)MTOT*EMB];      // x lo  [m][k]
__device__ __half g_wqkv[(size_t)3*EMB*EMB];   // [Wq^T;Wk^T;Wv^T] hi [n][k]
__device__ __half g_wo[(size_t)EMB*EMB];       // Wo^T hi [n][k]

#define QKV_ELEMS ((size_t)BATCH*NH*SEQ*HD)
__device__ __half g_qh[QKV_ELEMS], g_ql[QKV_ELEMS];   // Q hi/lo [B,H,S,D]
__device__ __half g_kh[QKV_ELEMS];                    // K hi only
__device__ __half g_vh[QKV_ELEMS];                    // V hi only

__device__ __half g_cth[(size_t)MTOT*EMB];     // ctx hi [B,S,E]
__device__ __half g_ctl[(size_t)MTOT*EMB];     // ctx lo

// ---------------------------------------------------------------------------
__device__ __forceinline__ uint32_t smem_u32(const void* p) {
    uint32_t a;
    asm("{ .reg .u64 t; cvta.to.shared.u64 t, %1; cvt.u32.u64 %0, t; }"
        : "=r"(a) : "l"(p));
    return a;
}

#define LDM4(r, addr)                                                          \
    asm volatile("ldmatrix.sync.aligned.m8n8.x4.shared.b16 {%0,%1,%2,%3}, [%4];" \
                 : "=r"((r)[0]), "=r"((r)[1]), "=r"((r)[2]), "=r"((r)[3])      \
                 : "r"(addr))

#define LDM2(r, addr)                                                          \
    asm volatile("ldmatrix.sync.aligned.m8n8.x2.shared.b16 {%0,%1}, [%2];"     \
                 : "=r"((r)[0]), "=r"((r)[1]) : "r"(addr))

#define LDM2T(r, addr)                                                         \
    asm volatile("ldmatrix.sync.aligned.m8n8.x2.trans.shared.b16 {%0,%1}, [%2];" \
                 : "=r"((r)[0]), "=r"((r)[1]) : "r"(addr))

#define MMA_F16(d, a, b)                                                       \
    asm volatile("mma.sync.aligned.m16n8k16.row.col.f32.f16.f16.f32 "          \
                 "{%0,%1,%2,%3}, {%4,%5,%6,%7}, {%8,%9}, {%0,%1,%2,%3};"       \
                 : "+f"((d)[0]), "+f"((d)[1]), "+f"((d)[2]), "+f"((d)[3])      \
                 : "r"((a)[0]), "r"((a)[1]), "r"((a)[2]), "r"((a)[3]),         \
                   "r"((b)[0]), "r"((b)[1]))

#define CPASYNC16(sa, ga)                                                      \
    asm volatile("cp.async.cg.shared.global [%0], [%1], 16;"                   \
                 :: "r"(sa), "l"(ga))

__device__ __forceinline__ uint32_t pack_hilo_h(float x, float y, uint32_t& lo) {
    __half hx = __float2half_rn(x), hy = __float2half_rn(y);
    __half lx = __float2half_rn(x - __half2float(hx));
    __half ly = __float2half_rn(y - __half2float(hy));
    __half2 h2 = __halves2half2(hx, hy);
    __half2 l2 = __halves2half2(lx, ly);
    lo = *reinterpret_cast<uint32_t*>(&l2);
    return *reinterpret_cast<uint32_t*>(&h2);
}

// ---------------------------------------------------------------------------
// fp32 -> (hi, lo) fp16 split. One float4 per thread.
// ---------------------------------------------------------------------------
__global__ __launch_bounds__(256) void cvt_hilo(const float* __restrict__ X,
                                                __half* __restrict__ H,
                                                __half* __restrict__ L)
{
    int i = blockIdx.x * 256 + threadIdx.x;
    float4 v = reinterpret_cast<const float4*>(X)[i];
    uint2 hh, ll;
    hh.x = pack_hilo_h(v.x, v.y, ll.x);
    hh.y = pack_hilo_h(v.z, v.w, ll.y);
    reinterpret_cast<uint2*>(H)[i] = hh;
    reinterpret_cast<uint2*>(L)[i] = ll;
}

// ---------------------------------------------------------------------------
// Transpose + fp16 round (hi only): W[k][n] fp32 -> T[n][k] fp16
// ---------------------------------------------------------------------------
__global__ __launch_bounds__(256) void transcvt_w(const float* __restrict__ W,
                                                  __half* __restrict__ Th)
{
    __shared__ float tile[32][33];
    int x = blockIdx.x * 32 + threadIdx.x;   // n
    int y = blockIdx.y * 32 + threadIdx.y;   // k
#pragma unroll
    for (int j = 0; j < 32; j += 8)
        tile[threadIdx.y + j][threadIdx.x] = W[(size_t)(y + j) * EMB + x];
    __syncthreads();
    int xo = blockIdx.y * 32 + threadIdx.x;  // k
    int yo = blockIdx.x * 32 + threadIdx.y;  // n
#pragma unroll
    for (int j = 0; j < 32; j += 8)
        Th[(size_t)(yo + j) * EMB + xo] = __float2half_rn(tile[threadIdx.x][threadIdx.y + j]);
}

// ---------------------------------------------------------------------------
// mma.sync fp16x2 GEMM: C[4096,N] = (Ah+Al) @ Bh^T    (B split dropped)
// CTA tile 128(M) x 256(N), BK=64, 8 warps (2M x 4N), warp tile 64x64.
// Double-buffered cp.async; rows padded to 144B (validated conflict-free).
// MODE 0: N=3072 merged QKV -> scatter Q(hi+lo)/K(hi)/V(hi) to [B,H,S,D].
// MODE 1: N=1024 out-proj -> fp32 row-major.
// ---------------------------------------------------------------------------
#define TROW    144
#define A_TILE  (128 * TROW)               // 18432
#define B_TILE  (256 * TROW)               // 36864
#define BUF_B2  (2 * A_TILE + B_TILE)      // 73728
#define GSMEM_BYTES (2 * BUF_B2)           // 147456

template<int MODE>
__global__ __launch_bounds__(256) void gemm_mma(const __half* __restrict__ Ah,
                                                const __half* __restrict__ Al,
                                                const __half* __restrict__ Bh,
                                                float* __restrict__ Cout,
                                                __half* __restrict__ Qh,
                                                __half* __restrict__ Ql,
                                                __half* __restrict__ Kh,
                                                __half* __restrict__ Vh)
{
    extern __shared__ char smem[];
    const uint32_t sbase = smem_u32(smem);
    const int t  = threadIdx.x;
    const int l  = t & 31;
    const int w  = t >> 5;
    const int wm = w & 1;                  // 2 in M
    const int wn = w >> 1;                 // 4 in N
    const int m0 = blockIdx.y * 128;
    const int n0 = blockIdx.x * 256;

    float acc[4][8][4];
#pragma unroll
    for (int a = 0; a < 4; a++)
#pragma unroll
        for (int b = 0; b < 8; b++)
#pragma unroll
            for (int c = 0; c < 4; c++) acc[a][b][c] = 0.f;

    const char* gah = (const char*)(Ah + (size_t)m0 * EMB);
    const char* gal = (const char*)(Al + (size_t)m0 * EMB);
    const char* gbh = (const char*)(Bh + (size_t)n0 * EMB);

    auto load_chunk = [&](int kc, int buf) {
        uint32_t s0 = sbase + buf * BUF_B2;
#pragma unroll
        for (int i = 0; i < 4; i++) {          // A hi+lo: 128 rows x 8 segs
            int e = t + i * 256;
            int row = e >> 3, seg = e & 7;
            int go = row * (EMB * 2) + kc * 128 + seg * 16;
            CPASYNC16(s0 + row * TROW + seg * 16, gah + go);
            CPASYNC16(s0 + A_TILE + row * TROW + seg * 16, gal + go);
        }
#pragma unroll
        for (int i = 0; i < 8; i++) {          // B hi: 256 rows x 8 segs
            int e = t + i * 256;
            int row = e >> 3, seg = e & 7;
            CPASYNC16(s0 + 2 * A_TILE + row * TROW + seg * 16,
                      gbh + row * (EMB * 2) + kc * 128 + seg * 16);
        }
        asm volatile("cp.async.commit_group;" ::: "memory");
    };

    load_chunk(0, 0);

    for (int c = 0; c < 16; c++) {
        asm volatile("cp.async.wait_group 0;" ::: "memory");
        __syncthreads();
        if (c + 1 < 16) load_chunk(c + 1, (c + 1) & 1);

        uint32_t s0 = sbase + (c & 1) * BUF_B2;
        uint32_t aH = s0 + (wm * 64 + (l & 15)) * TROW + (l >> 4) * 16;
        uint32_t aL = aH + A_TILE;
        uint32_t bH = s0 + 2 * A_TILE + (wn * 64 + (l & 7)) * TROW
                    + ((l >> 3) & 1) * 16;

#pragma unroll
        for (int ks = 0; ks < 4; ks++) {
            uint32_t ah[4][4], al[4][4];
#pragma unroll
            for (int ma = 0; ma < 4; ma++) {
                LDM4(ah[ma], aH + ma * 16 * TROW + ks * 32);
                LDM4(al[ma], aL + ma * 16 * TROW + ks * 32);
            }
#pragma unroll
            for (int nb = 0; nb < 8; nb++) {
                uint32_t bh[2];
                LDM2(bh, bH + nb * 8 * TROW + ks * 32);
#pragma unroll
                for (int ma = 0; ma < 4; ma++) {
                    MMA_F16(acc[ma][nb], ah[ma], bh);
                    MMA_F16(acc[ma][nb], al[ma], bh);
                }
            }
        }
    }

    // Epilogue
#pragma unroll
    for (int ma = 0; ma < 4; ma++) {
#pragma unroll
        for (int nb = 0; nb < 8; nb++) {
            int n = n0 + wn * 64 + nb * 8 + (l & 3) * 2;
#pragma unroll
            for (int half = 0; half < 2; half++) {
                int m = m0 + wm * 64 + ma * 16 + (l >> 2) + half * 8;
                float vx = acc[ma][nb][half * 2];
                float vy = acc[ma][nb][half * 2 + 1];
                if (MODE == 0) {
                    int which = n >> 10;          // 0=Q 1=K 2=V
                    int nn = n & 1023;
                    int h = nn >> 6, d = nn & 63;
                    int b = m >> 11, s = m & 2047;
                    size_t idx = ((size_t)(b * NH + h) * SEQ + s) * HD + d;
                    uint32_t lo, hi = pack_hilo_h(vx, vy, lo);
                    if (which == 0) {
                        *reinterpret_cast<uint32_t*>(Qh + idx) = hi;
                        *reinterpret_cast<uint32_t*>(Ql + idx) = lo;
                    } else if (which == 1) {
                        *reinterpret_cast<uint32_t*>(Kh + idx) = hi;
                    } else {
                        *reinterpret_cast<uint32_t*>(Vh + idx) = hi;
                    }
                } else {
                    *reinterpret_cast<float2*>(Cout + (size_t)m * EMB + n) =
                        make_float2(vx, vy);
                }
            }
        }
    }
}

// ---------------------------------------------------------------------------
// Flash attention, causal, mma.sync fp16x2, FA2 style.
// BM=64 (4 warps x m16), BN=64, D=64, 128 threads.
// smem: Qh/Ql (2x8KB) + double-buffered {Kh,Vh} (2 x 16KB) = 48KB.
// S = (Qh+Ql)@Kh^T (2 MMA);  O += (Ph+Pl)@Vh (2 MMA).
// ---------------------------------------------------------------------------
#define ASW(base, row, seg) ((base) + (uint32_t)(row) * 128u +                 \
                             (uint32_t)(((seg) ^ ((row) & 7)) * 16))
#define ATTN_SMEM (16384 + 2 * 16384)   // 49152

__global__ __launch_bounds__(128) void attn_mma()
{
    extern __shared__ char smc[];
    const uint32_t sb = smem_u32(smc);
    const int t = threadIdx.x, l = t & 31, w = t >> 5;
    const int bh = blockIdx.y;
    const int rb = (gridDim.x - 1) - blockIdx.x;   // heavy blocks first
    const int m0 = rb * 64;

    const uint32_t QH = sb, QL = sb + 8192;
    const uint32_t KVB = sb + 16384;               // + buf*16384

    // Preload Q hi/lo tile
    {
        size_t off = ((size_t)bh * SEQ + m0) * HD;
        const char* gh = (const char*)(g_qh + off);
        const char* gl = (const char*)(g_ql + off);
#pragma unroll
        for (int i = 0; i < 4; i++) {
            int e = t + i * 128, row = e >> 3, seg = e & 7;
            int go = row * 128 + seg * 16;
            CPASYNC16(ASW(QH, row, seg), gh + go);
            CPASYNC16(ASW(QL, row, seg), gl + go);
        }
        asm volatile("cp.async.commit_group;" ::: "memory");
    }

    auto load_kv = [&](int jb, int buf) {
        uint32_t base = KVB + buf * 16384;
        size_t off = ((size_t)bh * SEQ + jb * 64) * HD;
        const char* sk = (const char*)(g_kh + off);
        const char* sv = (const char*)(g_vh + off);
#pragma unroll
        for (int i = 0; i < 4; i++) {
            int e = t + i * 128, row = e >> 3, seg = e & 7;
            int go = row * 128 + seg * 16;
            CPASYNC16(ASW(base,        row, seg), sk + go);
            CPASYNC16(ASW(base + 8192, row, seg), sv + go);
        }
        asm volatile("cp.async.commit_group;" ::: "memory");
    };

    load_kv(0, 0);
    asm volatile("cp.async.wait_group 0;" ::: "memory");
    __syncthreads();

    // Q A-fragments (hi/lo)
    uint32_t qh[4][4], ql[4][4];
    {
        int row = w * 16 + (l & 15);
#pragma unroll
        for (int kt = 0; kt < 4; kt++) {
            LDM4(qh[kt], ASW(QH, row, kt * 2 + (l >> 4)));
            LDM4(ql[kt], ASW(QL, row, kt * 2 + (l >> 4)));
        }
    }

    float oacc[8][4];
#pragma unroll
    for (int d = 0; d < 8; d++)
#pragma unroll
        for (int j = 0; j < 4; j++) oacc[d][j] = 0.f;
    float mi0 = -1e30f, mi1 = -1e30f, li0 = 0.f, li1 = 0.f;

    const int r0 = m0 + w * 16 + (l >> 2);

    for (int jb = 0; jb <= rb; jb++) {
        const int buf = jb & 1;
        if (jb > 0) {
            asm volatile("cp.async.wait_group 0;" ::: "memory");
            __syncthreads();
        }
        if (jb < rb) load_kv(jb + 1, buf ^ 1);

        const uint32_t Kb = KVB + buf * 16384;
        const uint32_t Vb = Kb + 8192;

        // S = Q @ K^T (fp16x2)
        float sacc[8][4];
#pragma unroll
        for (int nt = 0; nt < 8; nt++)
#pragma unroll
            for (int j = 0; j < 4; j++) sacc[nt][j] = 0.f;

#pragma unroll
        for (int nt = 0; nt < 8; nt++) {
            int row = nt * 8 + (l & 7);
#pragma unroll
            for (int ks = 0; ks < 4; ks++) {
                uint32_t kh[2];
                LDM2(kh, ASW(Kb, row, ks * 2 + ((l >> 3) & 1)));
                MMA_F16(sacc[nt], qh[ks], kh);
                MMA_F16(sacc[nt], ql[ks], kh);
            }
        }

        // scale + causal mask + online softmax
        const bool diag = (jb == rb);
        float rmax0 = -1e30f, rmax1 = -1e30f;
#pragma unroll
        for (int nt = 0; nt < 8; nt++) {
            int cj = jb * 64 + nt * 8 + 2 * (l & 3);
            float s0 = sacc[nt][0] * 0.125f;
            float s1 = sacc[nt][1] * 0.125f;
            float s2 = sacc[nt][2] * 0.125f;
            float s3 = sacc[nt][3] * 0.125f;
            if (diag) {
                if (cj     > r0)     s0 = -1e30f;
                if (cj + 1 > r0)     s1 = -1e30f;
                if (cj     > r0 + 8) s2 = -1e30f;
                if (cj + 1 > r0 + 8) s3 = -1e30f;
            }
            sacc[nt][0] = s0; sacc[nt][1] = s1;
            sacc[nt][2] = s2; sacc[nt][3] = s3;
            rmax0 = fmaxf(rmax0, fmaxf(s0, s1));
            rmax1 = fmaxf(rmax1, fmaxf(s2, s3));
        }
        rmax0 = fmaxf(rmax0, __shfl_xor_sync(0xffffffffu, rmax0, 1));
        rmax0 = fmaxf(rmax0, __shfl_xor_sync(0xffffffffu, rmax0, 2));
        rmax1 = fmaxf(rmax1, __shfl_xor_sync(0xffffffffu, rmax1, 1));
        rmax1 = fmaxf(rmax1, __shfl_xor_sync(0xffffffffu, rmax1, 2));

        float mn0 = fmaxf(mi0, rmax0), mn1 = fmaxf(mi1, rmax1);
        float a0 = __expf(mi0 - mn0),  a1 = __expf(mi1 - mn1);
        float sum0 = 0.f, sum1 = 0.f;
#pragma unroll
        for (int nt = 0; nt < 8; nt++) {
            float p0 = __expf(sacc[nt][0] - mn0);
            float p1 = __expf(sacc[nt][1] - mn0);
            float p2 = __expf(sacc[nt][2] - mn1);
            float p3 = __expf(sacc[nt][3] - mn1);
            sacc[nt][0] = p0; sacc[nt][1] = p1;
            sacc[nt][2] = p2; sacc[nt][3] = p3;
            sum0 += p0 + p1; sum1 += p2 + p3;
        }
        sum0 += __shfl_xor_sync(0xffffffffu, sum0, 1);
        sum0 += __shfl_xor_sync(0xffffffffu, sum0, 2);
        sum1 += __shfl_xor_sync(0xffffffffu, sum1, 1);
        sum1 += __shfl_xor_sync(0xffffffffu, sum1, 2);
        li0 = li0 * a0 + sum0;  mi0 = mn0;
        li1 = li1 * a1 + sum1;  mi1 = mn1;
#pragma unroll
        for (int d = 0; d < 8; d++) {
            oacc[d][0] *= a0; oacc[d][1] *= a0;
            oacc[d][2] *= a1; oacc[d][3] *= a1;
        }

        // O += P @ V (fp16x2). S-frag pair == A-frag for k16.
#pragma unroll
        for (int ks = 0; ks < 4; ks++) {
            uint32_t ph[4], pl[4];
            ph[0] = pack_hilo_h(sacc[2*ks][0],   sacc[2*ks][1],   pl[0]);
            ph[1] = pack_hilo_h(sacc[2*ks][2],   sacc[2*ks][3],   pl[1]);
            ph[2] = pack_hilo_h(sacc[2*ks+1][0], sacc[2*ks+1][1], pl[2]);
            ph[3] = pack_hilo_h(sacc[2*ks+1][2], sacc[2*ks+1][3], pl[3]);
            int row = ks * 16 + (l & 7) + 8 * ((l >> 3) & 1);
#pragma unroll
            for (int dt = 0; dt < 8; dt++) {
                uint32_t vh[2];
                LDM2T(vh, ASW(Vb, row, dt));
                MMA_F16(oacc[dt], ph, vh);
                MMA_F16(oacc[dt], pl, vh);
            }
        }
    }

    // Epilogue: normalize, write ctx hi/lo fp16 [B,S,E]
    {
        float inv0 = 1.f / li0, inv1 = 1.f / li1;
        int b = bh >> 4, h = bh & 15;
        int row = m0 + w * 16 + (l >> 2);
        size_t base = ((size_t)(b * SEQ) + row) * EMB + h * 64 + 2 * (l & 3);
#pragma unroll
        for (int dt = 0; dt < 8; dt++) {
            uint32_t lo0, hi0 = pack_hilo_h(oacc[dt][0] * inv0,
                                            oacc[dt][1] * inv0, lo0);
            uint32_t lo1, hi1 = pack_hilo_h(oacc[dt][2] * inv1,
                                            oacc[dt][3] * inv1, lo1);
            *reinterpret_cast<uint32_t*>(g_cth + base + dt * 8)           = hi0;
            *reinterpret_cast<uint32_t*>(g_ctl + base + dt * 8)           = lo0;
            *reinterpret_cast<uint32_t*>(g_cth + base + 8 * EMB + dt * 8) = hi1;
            *reinterpret_cast<uint32_t*>(g_ctl + base + 8 * EMB + dt * 8) = lo1;
        }
    }
}

// ---------------------------------------------------------------------------
extern "C" void kernel_launch(void* const* d_in, const int* in_sizes, int n_in,
                              void* d_out, int out_size)
{
    const float* x  = (const float*)d_in[0];
    const float* wq = (const float*)d_in[1];
    const float* wk = (const float*)d_in[2];
    const float* wv = (const float*)d_in[3];
    const float* wo = (const float*)d_in[4];
    float* out = (float*)d_out;

    void *pxh, *pxl, *pwqkv, *pwo, *pqh, *pql, *pkh, *pvh, *pcth, *pctl;
    cudaGetSymbolAddress(&pxh,   g_xh);
    cudaGetSymbolAddress(&pxl,   g_xl);
    cudaGetSymbolAddress(&pwqkv, g_wqkv);
    cudaGetSymbolAddress(&pwo,   g_wo);
    cudaGetSymbolAddress(&pqh,   g_qh);
    cudaGetSymbolAddress(&pql,   g_ql);
    cudaGetSymbolAddress(&pkh,   g_kh);
    cudaGetSymbolAddress(&pvh,   g_vh);
    cudaGetSymbolAddress(&pcth,  g_cth);
    cudaGetSymbolAddress(&pctl,  g_ctl);

    __half* xh   = (__half*)pxh;
    __half* xl   = (__half*)pxl;
    __half* wqkv = (__half*)pwqkv;

    cudaFuncSetAttribute(attn_mma,
                         cudaFuncAttributeMaxDynamicSharedMemorySize, ATTN_SMEM);
    cudaFuncSetAttribute(gemm_mma<0>,
                         cudaFuncAttributeMaxDynamicSharedMemorySize, GSMEM_BYTES);
    cudaFuncSetAttribute(gemm_mma<1>,
                         cudaFuncAttributeMaxDynamicSharedMemorySize, GSMEM_BYTES);

    dim3 gw(32, 32), bw(32, 8);

    // Launches 0-3: weight transposes (so ncu -s 5 lands on the QKV GEMM)
    transcvt_w<<<gw, bw>>>(wq, wqkv);
    transcvt_w<<<gw, bw>>>(wk, wqkv + (size_t)EMB * EMB);
    transcvt_w<<<gw, bw>>>(wv, wqkv + (size_t)2 * EMB * EMB);
    transcvt_w<<<gw, bw>>>(wo, (__half*)pwo);

    // Launch 4: x split
    cvt_hilo<<<MTOT * EMB / 4 / 256, 256>>>(x, xh, xl);

    // Launch 5: merged QKV GEMM [4096 x 3072]
    gemm_mma<0><<<dim3(3 * EMB / 256, MTOT / 128), 256, GSMEM_BYTES>>>(
        xh, xl, wqkv, nullptr,
        (__half*)pqh, (__half*)pql, (__half*)pkh, (__half*)pvh);

    // Launch 6: attention
    attn_mma<<<dim3(SEQ / 64, BATCH * NH), 128, ATTN_SMEM>>>();

    // Launch 7: out projection [4096 x 1024]
    gemm_mma<1><<<dim3(EMB / 256, MTOT / 128), 256, GSMEM_BYTES>>>(
        (__half*)pcth, (__half*)pctl, (__half*)pwo, out,
        nullptr, nullptr, nullptr, nullptr);
}

// round 14
// speedup vs baseline: 4.9041x; 1.0936x over previous
#include <cuda_runtime.h>
#include <cuda_fp16.h>
#include <cstdint>

// Problem constants
#define EMB   1024
#define NH    16
#define HD    64
#define BATCH 2
#define SEQ   2048
#define MTOT  (BATCH*SEQ)   // 4096

// Scratch (device globals — no allocation allowed). All fp16.
__device__ __half g_xh[(size_t)MTOT*EMB];      // x hi  [m][k]
__device__ __half g_xl[(size_t)MTOT*EMB];      // x lo  [m][k]
__device__ __half g_wqkv[(size_t)3*EMB*EMB];   // [Wq^T;Wk^T;Wv^T] hi [n][k]
__device__ __half g_wo[(size_t)EMB*EMB];       // Wo^T hi [n][k]

#define QKV_ELEMS ((size_t)BATCH*NH*SEQ*HD)
__device__ __half g_qh[QKV_ELEMS], g_ql[QKV_ELEMS];   // Q hi/lo [B,H,S,D]
__device__ __half g_kh[QKV_ELEMS];                    // K hi only
__device__ __half g_vh[QKV_ELEMS];                    // V hi only

__device__ __half g_cth[(size_t)MTOT*EMB];     // ctx hi [B,S,E]

// ---------------------------------------------------------------------------
__device__ __forceinline__ uint32_t smem_u32(const void* p) {
    uint32_t a;
    asm("{ .reg .u64 t; cvta.to.shared.u64 t, %1; cvt.u32.u64 %0, t; }"
        : "=r"(a) : "l"(p));
    return a;
}

#define LDM4(r, addr)                                                          \
    asm volatile("ldmatrix.sync.aligned.m8n8.x4.shared.b16 {%0,%1,%2,%3}, [%4];" \
                 : "=r"((r)[0]), "=r"((r)[1]), "=r"((r)[2]), "=r"((r)[3])      \
                 : "r"(addr))

#define LDM2(r, addr)                                                          \
    asm volatile("ldmatrix.sync.aligned.m8n8.x2.shared.b16 {%0,%1}, [%2];"     \
                 : "=r"((r)[0]), "=r"((r)[1]) : "r"(addr))

#define LDM2T(r, addr)                                                         \
    asm volatile("ldmatrix.sync.aligned.m8n8.x2.trans.shared.b16 {%0,%1}, [%2];" \
                 : "=r"((r)[0]), "=r"((r)[1]) : "r"(addr))

#define MMA_F16(d, a, b)                                                       \
    asm volatile("mma.sync.aligned.m16n8k16.row.col.f32.f16.f16.f32 "          \
                 "{%0,%1,%2,%3}, {%4,%5,%6,%7}, {%8,%9}, {%0,%1,%2,%3};"       \
                 : "+f"((d)[0]), "+f"((d)[1]), "+f"((d)[2]), "+f"((d)[3])      \
                 : "r"((a)[0]), "r"((a)[1]), "r"((a)[2]), "r"((a)[3]),         \
                   "r"((b)[0]), "r"((b)[1]))

#define CPASYNC16(sa, ga)                                                      \
    asm volatile("cp.async.cg.shared.global [%0], [%1], 16;"                   \
                 :: "r"(sa), "l"(ga))

__device__ __forceinline__ uint32_t pack_hilo_h(float x, float y, uint32_t& lo) {
    __half hx = __float2half_rn(x), hy = __float2half_rn(y);
    __half lx = __float2half_rn(x - __half2float(hx));
    __half ly = __float2half_rn(y - __half2float(hy));
    __half2 h2 = __halves2half2(hx, hy);
    __half2 l2 = __halves2half2(lx, ly);
    lo = *reinterpret_cast<uint32_t*>(&l2);
    return *reinterpret_cast<uint32_t*>(&h2);
}

__device__ __forceinline__ uint32_t pack_h(float x, float y) {
    __half2 h2 = __halves2half2(__float2half_rn(x), __float2half_rn(y));
    return *reinterpret_cast<uint32_t*>(&h2);
}

// ---------------------------------------------------------------------------
// fp32 -> (hi, lo) fp16 split. One float4 per thread.
// ---------------------------------------------------------------------------
__global__ __launch_bounds__(256) void cvt_hilo(const float* __restrict__ X,
                                                __half* __restrict__ H,
                                                __half* __restrict__ L)
{
    int i = blockIdx.x * 256 + threadIdx.x;
    float4 v = reinterpret_cast<const float4*>(X)[i];
    uint2 hh, ll;
    hh.x = pack_hilo_h(v.x, v.y, ll.x);
    hh.y = pack_hilo_h(v.z, v.w, ll.y);
    reinterpret_cast<uint2*>(H)[i] = hh;
    reinterpret_cast<uint2*>(L)[i] = ll;
}

// ---------------------------------------------------------------------------
// Transpose + fp16 round (hi only): W[k][n] fp32 -> T[n][k] fp16
// ---------------------------------------------------------------------------
__global__ __launch_bounds__(256) void transcvt_w(const float* __restrict__ W,
                                                  __half* __restrict__ Th)
{
    __shared__ float tile[32][33];
    int x = blockIdx.x * 32 + threadIdx.x;   // n
    int y = blockIdx.y * 32 + threadIdx.y;   // k
#pragma unroll
    for (int j = 0; j < 32; j += 8)
        tile[threadIdx.y + j][threadIdx.x] = W[(size_t)(y + j) * EMB + x];
    __syncthreads();
    int xo = blockIdx.y * 32 + threadIdx.x;  // k
    int yo = blockIdx.x * 32 + threadIdx.y;  // n
#pragma unroll
    for (int j = 0; j < 32; j += 8)
        Th[(size_t)(yo + j) * EMB + xo] = __float2half_rn(tile[threadIdx.x][threadIdx.y + j]);
}

// ---------------------------------------------------------------------------
// mma.sync fp16 GEMM: C[4096,N] = (Ah [+ Al]) @ Bh^T
// CTA tile 128(M) x 256(N), BK=64, 8 warps (2M x 4N), warp tile 64x64.
// The Al (lo) term is issued only where the output needs it:
//   MODE 0 (QKV, N=3072): Q columns (blockIdx.x < 4) use 2 terms;
//     K/V columns 1 term (their fp16 storage rounding dominates anyway).
//   MODE 1 (out-proj, N=1024): 1 term (ctx stored hi-only).
// ---------------------------------------------------------------------------
#define TROW    144
#define A_TILE  (128 * TROW)               // 18432
#define B_TILE  (256 * TROW)               // 36864
#define BUF_B2  (2 * A_TILE + B_TILE)      // 73728
#define GSMEM_BYTES (2 * BUF_B2)           // 147456

template<int MODE>
__global__ __launch_bounds__(256) void gemm_mma(const __half* __restrict__ Ah,
                                                const __half* __restrict__ Al,
                                                const __half* __restrict__ Bh,
                                                float* __restrict__ Cout,
                                                __half* __restrict__ Qh,
                                                __half* __restrict__ Ql,
                                                __half* __restrict__ Kh,
                                                __half* __restrict__ Vh)
{
    extern __shared__ char smem[];
    const uint32_t sbase = smem_u32(smem);
    const int t  = threadIdx.x;
    const int l  = t & 31;
    const int w  = t >> 5;
    const int wm = w & 1;                  // 2 in M
    const int wn = w >> 1;                 // 4 in N
    const int m0 = blockIdx.y * 128;
    const int n0 = blockIdx.x * 256;
    const bool use_lo = (MODE == 0) && (blockIdx.x < 4);   // Q columns only

    float acc[4][8][4];
#pragma unroll
    for (int a = 0; a < 4; a++)
#pragma unroll
        for (int b = 0; b < 8; b++)
#pragma unroll
            for (int c = 0; c < 4; c++) acc[a][b][c] = 0.f;

    const char* gah = (const char*)(Ah + (size_t)m0 * EMB);
    const char* gal = (const char*)(Al + (size_t)m0 * EMB);
    const char* gbh = (const char*)(Bh + (size_t)n0 * EMB);

    auto load_chunk = [&](int kc, int buf) {
        uint32_t s0 = sbase + buf * BUF_B2;
#pragma unroll
        for (int i = 0; i < 4; i++) {          // A hi (+lo): 128 rows x 8 segs
            int e = t + i * 256;
            int row = e >> 3, seg = e & 7;
            int go = row * (EMB * 2) + kc * 128 + seg * 16;
            CPASYNC16(s0 + row * TROW + seg * 16, gah + go);
            if (use_lo)
                CPASYNC16(s0 + A_TILE + row * TROW + seg * 16, gal + go);
        }
#pragma unroll
        for (int i = 0; i < 8; i++) {          // B hi: 256 rows x 8 segs
            int e = t + i * 256;
            int row = e >> 3, seg = e & 7;
            CPASYNC16(s0 + 2 * A_TILE + row * TROW + seg * 16,
                      gbh + row * (EMB * 2) + kc * 128 + seg * 16);
        }
        asm volatile("cp.async.commit_group;" ::: "memory");
    };

    load_chunk(0, 0);

    for (int c = 0; c < 16; c++) {
        asm volatile("cp.async.wait_group 0;" ::: "memory");
        __syncthreads();
        if (c + 1 < 16) load_chunk(c + 1, (c + 1) & 1);

        uint32_t s0 = sbase + (c & 1) * BUF_B2;
        uint32_t aH = s0 + (wm * 64 + (l & 15)) * TROW + (l >> 4) * 16;
        uint32_t aL = aH + A_TILE;
        uint32_t bH = s0 + 2 * A_TILE + (wn * 64 + (l & 7)) * TROW
                    + ((l >> 3) & 1) * 16;

#pragma unroll
        for (int ks = 0; ks < 4; ks++) {
            uint32_t ah[4][4], al[4][4];
#pragma unroll
            for (int ma = 0; ma < 4; ma++) {
                LDM4(ah[ma], aH + ma * 16 * TROW + ks * 32);
                if (use_lo) LDM4(al[ma], aL + ma * 16 * TROW + ks * 32);
            }
#pragma unroll
            for (int nb = 0; nb < 8; nb++) {
                uint32_t bh[2];
                LDM2(bh, bH + nb * 8 * TROW + ks * 32);
#pragma unroll
                for (int ma = 0; ma < 4; ma++) {
                    MMA_F16(acc[ma][nb], ah[ma], bh);
                    if (use_lo) MMA_F16(acc[ma][nb], al[ma], bh);
                }
            }
        }
    }

    // Epilogue
#pragma unroll
    for (int ma = 0; ma < 4; ma++) {
#pragma unroll
        for (int nb = 0; nb < 8; nb++) {
            int n = n0 + wn * 64 + nb * 8 + (l & 3) * 2;
#pragma unroll
            for (int half = 0; half < 2; half++) {
                int m = m0 + wm * 64 + ma * 16 + (l >> 2) + half * 8;
                float vx = acc[ma][nb][half * 2];
                float vy = acc[ma][nb][half * 2 + 1];
                if (MODE == 0) {
                    int which = n >> 10;          // 0=Q 1=K 2=V
                    int nn = n & 1023;
                    int h = nn >> 6, d = nn & 63;
                    int b = m >> 11, s = m & 2047;
                    size_t idx = ((size_t)(b * NH + h) * SEQ + s) * HD + d;
                    if (which == 0) {
                        uint32_t lo, hi = pack_hilo_h(vx, vy, lo);
                        *reinterpret_cast<uint32_t*>(Qh + idx) = hi;
                        *reinterpret_cast<uint32_t*>(Ql + idx) = lo;
                    } else if (which == 1) {
                        *reinterpret_cast<uint32_t*>(Kh + idx) = pack_h(vx, vy);
                    } else {
                        *reinterpret_cast<uint32_t*>(Vh + idx) = pack_h(vx, vy);
                    }
                } else {
                    *reinterpret_cast<float2*>(Cout + (size_t)m * EMB + n) =
                        make_float2(vx, vy);
                }
            }
        }
    }
}

// ---------------------------------------------------------------------------
// Flash attention, causal, mma.sync fp16x2, FA2 style.
// BM=64 (4 warps x m16), BN=64, D=64, 128 threads.
// smem: Qh/Ql (2x8KB) + double-buffered {Kh,Vh} (2 x 16KB) = 48KB.
// S = (Qh+Ql)@Kh^T (2 MMA);  O += (Ph+Pl)@Vh (2 MMA).
// ---------------------------------------------------------------------------
#define ASW(base, row, seg) ((base) + (uint32_t)(row) * 128u +                 \
                             (uint32_t)(((seg) ^ ((row) & 7)) * 16))
#define ATTN_SMEM (16384 + 2 * 16384)   // 49152

__global__ __launch_bounds__(128) void attn_mma()
{
    extern __shared__ char smc[];
    const uint32_t sb = smem_u32(smc);
    const int t = threadIdx.x, l = t & 31, w = t >> 5;
    const int bh = blockIdx.y;
    const int rb = (gridDim.x - 1) - blockIdx.x;   // heavy blocks first
    const int m0 = rb * 64;

    const uint32_t QH = sb, QL = sb + 8192;
    const uint32_t KVB = sb + 16384;               // + buf*16384

    // Preload Q hi/lo tile
    {
        size_t off = ((size_t)bh * SEQ + m0) * HD;
        const char* gh = (const char*)(g_qh + off);
        const char* gl = (const char*)(g_ql + off);
#pragma unroll
        for (int i = 0; i < 4; i++) {
            int e = t + i * 128, row = e >> 3, seg = e & 7;
            int go = row * 128 + seg * 16;
            CPASYNC16(ASW(QH, row, seg), gh + go);
            CPASYNC16(ASW(QL, row, seg), gl + go);
        }
        asm volatile("cp.async.commit_group;" ::: "memory");
    }

    auto load_kv = [&](int jb, int buf) {
        uint32_t base = KVB + buf * 16384;
        size_t off = ((size_t)bh * SEQ + jb * 64) * HD;
        const char* sk = (const char*)(g_kh + off);
        const char* sv = (const char*)(g_vh + off);
#pragma unroll
        for (int i = 0; i < 4; i++) {
            int e = t + i * 128, row = e >> 3, seg = e & 7;
            int go = row * 128 + seg * 16;
            CPASYNC16(ASW(base,        row, seg), sk + go);
            CPASYNC16(ASW(base + 8192, row, seg), sv + go);
        }
        asm volatile("cp.async.commit_group;" ::: "memory");
    };

    load_kv(0, 0);
    asm volatile("cp.async.wait_group 0;" ::: "memory");
    __syncthreads();

    // Q A-fragments (hi/lo)
    uint32_t qh[4][4], ql[4][4];
    {
        int row = w * 16 + (l & 15);
#pragma unroll
        for (int kt = 0; kt < 4; kt++) {
            LDM4(qh[kt], ASW(QH, row, kt * 2 + (l >> 4)));
            LDM4(ql[kt], ASW(QL, row, kt * 2 + (l >> 4)));
        }
    }

    float oacc[8][4];
#pragma unroll
    for (int d = 0; d < 8; d++)
#pragma unroll
        for (int j = 0; j < 4; j++) oacc[d][j] = 0.f;
    float mi0 = -1e30f, mi1 = -1e30f, li0 = 0.f, li1 = 0.f;

    const int r0 = m0 + w * 16 + (l >> 2);

    for (int jb = 0; jb <= rb; jb++) {
        const int buf = jb & 1;
        if (jb > 0) {
            asm volatile("cp.async.wait_group 0;" ::: "memory");
            __syncthreads();
        }
        if (jb < rb) load_kv(jb + 1, buf ^ 1);

        const uint32_t Kb = KVB + buf * 16384;
        const uint32_t Vb = Kb + 8192;

        // S = Q @ K^T (fp16x2)
        float sacc[8][4];
#pragma unroll
        for (int nt = 0; nt < 8; nt++)
#pragma unroll
            for (int j = 0; j < 4; j++) sacc[nt][j] = 0.f;

#pragma unroll
        for (int nt = 0; nt < 8; nt++) {
            int row = nt * 8 + (l & 7);
#pragma unroll
            for (int ks = 0; ks < 4; ks++) {
                uint32_t kh[2];
                LDM2(kh, ASW(Kb, row, ks * 2 + ((l >> 3) & 1)));
                MMA_F16(sacc[nt], qh[ks], kh);
                MMA_F16(sacc[nt], ql[ks], kh);
            }
        }

        // scale + causal mask + online softmax
        const bool diag = (jb == rb);
        float rmax0 = -1e30f, rmax1 = -1e30f;
#pragma unroll
        for (int nt = 0; nt < 8; nt++) {
            int cj = jb * 64 + nt * 8 + 2 * (l & 3);
            float s0 = sacc[nt][0] * 0.125f;
            float s1 = sacc[nt][1] * 0.125f;
            float s2 = sacc[nt][2] * 0.125f;
            float s3 = sacc[nt][3] * 0.125f;
            if (diag) {
                if (cj     > r0)     s0 = -1e30f;
                if (cj + 1 > r0)     s1 = -1e30f;
                if (cj     > r0 + 8) s2 = -1e30f;
                if (cj + 1 > r0 + 8) s3 = -1e30f;
            }
            sacc[nt][0] = s0; sacc[nt][1] = s1;
            sacc[nt][2] = s2; sacc[nt][3] = s3;
            rmax0 = fmaxf(rmax0, fmaxf(s0, s1));
            rmax1 = fmaxf(rmax1, fmaxf(s2, s3));
        }
        rmax0 = fmaxf(rmax0, __shfl_xor_sync(0xffffffffu, rmax0, 1));
        rmax0 = fmaxf(rmax0, __shfl_xor_sync(0xffffffffu, rmax0, 2));
        rmax1 = fmaxf(rmax1, __shfl_xor_sync(0xffffffffu, rmax1, 1));
        rmax1 = fmaxf(rmax1, __shfl_xor_sync(0xffffffffu, rmax1, 2));

        float mn0 = fmaxf(mi0, rmax0), mn1 = fmaxf(mi1, rmax1);
        float a0 = __expf(mi0 - mn0),  a1 = __expf(mi1 - mn1);
        float sum0 = 0.f, sum1 = 0.f;
#pragma unroll
        for (int nt = 0; nt < 8; nt++) {
            float p0 = __expf(sacc[nt][0] - mn0);
            float p1 = __expf(sacc[nt][1] - mn0);
            float p2 = __expf(sacc[nt][2] - mn1);
            float p3 = __expf(sacc[nt][3] - mn1);
            sacc[nt][0] = p0; sacc[nt][1] = p1;
            sacc[nt][2] = p2; sacc[nt][3] = p3;
            sum0 += p0 + p1; sum1 += p2 + p3;
        }
        sum0 += __shfl_xor_sync(0xffffffffu, sum0, 1);
        sum0 += __shfl_xor_sync(0xffffffffu, sum0, 2);
        sum1 += __shfl_xor_sync(0xffffffffu, sum1, 1);
        sum1 += __shfl_xor_sync(0xffffffffu, sum1, 2);
        li0 = li0 * a0 + sum0;  mi0 = mn0;
        li1 = li1 * a1 + sum1;  mi1 = mn1;
#pragma unroll
        for (int d = 0; d < 8; d++) {
            oacc[d][0] *= a0; oacc[d][1] *= a0;
            oacc[d][2] *= a1; oacc[d][3] *= a1;
        }

        // O += P @ V (fp16x2). S-frag pair == A-frag for k16.
#pragma unroll
        for (int ks = 0; ks < 4; ks++) {
            uint32_t ph[4], pl[4];
            ph[0] = pack_hilo_h(sacc[2*ks][0],   sacc[2*ks][1],   pl[0]);
            ph[1] = pack_hilo_h(sacc[2*ks][2],   sacc[2*ks][3],   pl[1]);
            ph[2] = pack_hilo_h(sacc[2*ks+1][0], sacc[2*ks+1][1], pl[2]);
            ph[3] = pack_hilo_h(sacc[2*ks+1][2], sacc[2*ks+1][3], pl[3]);
            int row = ks * 16 + (l & 7) + 8 * ((l >> 3) & 1);
#pragma unroll
            for (int dt = 0; dt < 8; dt++) {
                uint32_t vh[2];
                LDM2T(vh, ASW(Vb, row, dt));
                MMA_F16(oacc[dt], ph, vh);
                MMA_F16(oacc[dt], pl, vh);
            }
        }
    }

    // Epilogue: normalize, write ctx hi fp16 [B,S,E]
    {
        float inv0 = 1.f / li0, inv1 = 1.f / li1;
        int b = bh >> 4, h = bh & 15;
        int row = m0 + w * 16 + (l >> 2);
        size_t base = ((size_t)(b * SEQ) + row) * EMB + h * 64 + 2 * (l & 3);
#pragma unroll
        for (int dt = 0; dt < 8; dt++) {
            *reinterpret_cast<uint32_t*>(g_cth + base + dt * 8) =
                pack_h(oacc[dt][0] * inv0, oacc[dt][1] * inv0);
            *reinterpret_cast<uint32_t*>(g_cth + base + 8 * EMB + dt * 8) =
                pack_h(oacc[dt][2] * inv1, oacc[dt][3] * inv1);
        }
    }
}

// ---------------------------------------------------------------------------
extern "C" void kernel_launch(void* const* d_in, const int* in_sizes, int n_in,
                              void* d_out, int out_size)
{
    const float* x  = (const float*)d_in[0];
    const float* wq = (const float*)d_in[1];
    const float* wk = (const float*)d_in[2];
    const float* wv = (const float*)d_in[3];
    const float* wo = (const float*)d_in[4];
    float* out = (float*)d_out;

    void *pxh, *pxl, *pwqkv, *pwo, *pqh, *pql, *pkh, *pvh, *pcth;
    cudaGetSymbolAddress(&pxh,   g_xh);
    cudaGetSymbolAddress(&pxl,   g_xl);
    cudaGetSymbolAddress(&pwqkv, g_wqkv);
    cudaGetSymbolAddress(&pwo,   g_wo);
    cudaGetSymbolAddress(&pqh,   g_qh);
    cudaGetSymbolAddress(&pql,   g_ql);
    cudaGetSymbolAddress(&pkh,   g_kh);
    cudaGetSymbolAddress(&pvh,   g_vh);
    cudaGetSymbolAddress(&pcth,  g_cth);

    __half* xh   = (__half*)pxh;
    __half* xl   = (__half*)pxl;
    __half* wqkv = (__half*)pwqkv;

    cudaFuncSetAttribute(attn_mma,
                         cudaFuncAttributeMaxDynamicSharedMemorySize, ATTN_SMEM);
    cudaFuncSetAttribute(gemm_mma<0>,
                         cudaFuncAttributeMaxDynamicSharedMemorySize, GSMEM_BYTES);
    cudaFuncSetAttribute(gemm_mma<1>,
                         cudaFuncAttributeMaxDynamicSharedMemorySize, GSMEM_BYTES);

    dim3 gw(32, 32), bw(32, 8);

    // Weight transposes + x split
    transcvt_w<<<gw, bw>>>(wq, wqkv);
    transcvt_w<<<gw, bw>>>(wk, wqkv + (size_t)EMB * EMB);
    transcvt_w<<<gw, bw>>>(wv, wqkv + (size_t)2 * EMB * EMB);
    transcvt_w<<<gw, bw>>>(wo, (__half*)pwo);
    cvt_hilo<<<MTOT * EMB / 4 / 256, 256>>>(x, xh, xl);

    // Merged QKV GEMM [4096 x 3072]; Q columns 2-term, K/V 1-term
    gemm_mma<0><<<dim3(3 * EMB / 256, MTOT / 128), 256, GSMEM_BYTES>>>(
        xh, xl, wqkv, nullptr,
        (__half*)pqh, (__half*)pql, (__half*)pkh, (__half*)pvh);

    // Attention
    attn_mma<<<dim3(SEQ / 64, BATCH * NH), 128, ATTN_SMEM>>>();

    // Out projection [4096 x 1024], 1-term
    gemm_mma<1><<<dim3(EMB / 256, MTOT / 128), 256, GSMEM_BYTES>>>(
        (__half*)pcth, nullptr, (__half*)pwo, out,
        nullptr, nullptr, nullptr, nullptr);
}